// round 10
// baseline (speedup 1.0000x reference)
#include <cuda_runtime.h>
#include <cuda_bf16.h>
#include <math.h>
#include <stdint.h>

#define D_K    2048
#define B_F    4096
#define C_C    2048
#define NUMR   2
#define NEARK  3
#define MAXIT  15
#define MARGINF 1.0f

typedef unsigned long long u64;
#define KINF 0xFFFFFFFFFFFFFFFFULL

// ---------------------------------------------------------------------------
// Device scratch
// ---------------------------------------------------------------------------
__device__ float g_Dfc[(size_t)B_F * C_C];   // 32 MB
__device__ float g_Dcc[(size_t)C_C * C_C];   // 16 MB
__device__ float g_fn[B_F];
__device__ float g_cn[C_C];
__device__ int4  g_near[C_C];
__device__ float g_hinge[B_F];
__device__ __nv_bfloat16 g_fh[(size_t)B_F * D_K];
__device__ __nv_bfloat16 g_fl[(size_t)B_F * D_K];
__device__ __nv_bfloat16 g_ch[(size_t)C_C * D_K];
__device__ __nv_bfloat16 g_cl[(size_t)C_C * D_K];

// ---------------------------------------------------------------------------
// Baseline-PTX helpers (sm_80+ only; plain sm_103 target has no tcgen05)
// ---------------------------------------------------------------------------
__device__ __forceinline__ uint32_t smem_u32(const void* p) {
    uint32_t a;
    asm("{ .reg .u64 t; cvta.to.shared.u64 t, %1; cvt.u32.u64 %0, t; }" : "=r"(a) : "l"(p));
    return a;
}
__device__ __forceinline__ void cp16(uint32_t s, const void* g) {
    asm volatile("cp.async.cg.shared.global [%0], [%1], 16;" :: "r"(s), "l"(g));
}
#define CP_COMMIT() asm volatile("cp.async.commit_group;" ::: "memory")
#define CP_WAIT0()  asm volatile("cp.async.wait_group 0;" ::: "memory")

__device__ __forceinline__ void ldsm4(uint32_t& r0, uint32_t& r1, uint32_t& r2, uint32_t& r3,
                                      uint32_t addr) {
    asm volatile("ldmatrix.sync.aligned.m8n8.x4.shared.b16 {%0,%1,%2,%3}, [%4];"
                 : "=r"(r0), "=r"(r1), "=r"(r2), "=r"(r3) : "r"(addr));
}
__device__ __forceinline__ void mma16816(float c[4], const uint32_t a[4],
                                         uint32_t b0, uint32_t b1) {
    asm volatile("mma.sync.aligned.m16n8k16.row.col.f32.bf16.bf16.f32 "
                 "{%0,%1,%2,%3}, {%4,%5,%6,%7}, {%8,%9}, {%0,%1,%2,%3};"
                 : "+f"(c[0]), "+f"(c[1]), "+f"(c[2]), "+f"(c[3])
                 : "r"(a[0]), "r"(a[1]), "r"(a[2]), "r"(a[3]), "r"(b0), "r"(b1));
}

__device__ __forceinline__ u64 umin64(u64 a, u64 b) { return a < b ? a : b; }
__device__ __forceinline__ u64 umax64(u64 a, u64 b) { return a > b ? a : b; }
__device__ __forceinline__ u64 mkkey(float d, int idx) {
    return ((u64)__float_as_uint(d) << 32) | (uint32_t)idx;
}

// merge two sorted triples -> sorted top-3 of union (median network, verified)
__device__ __forceinline__ void merge3(u64& a0, u64& a1, u64& a2,
                                       u64 b0, u64 b1, u64 b2) {
    u64 mx0 = umax64(a0, b0);
    u64 mn1 = umin64(a1, b1);
    u64 r0 = umin64(a0, b0);
    u64 r1 = umin64(mx0, mn1);
    u64 r2 = umin64(umax64(mx0, mn1), umin64(a2, b2));
    a0 = r0; a1 = r1; a2 = r2;
}

// ---------------------------------------------------------------------------
// Fused fp32 -> (bf16 hi,lo) split + row norm. 128 threads, 4 float4/thread.
// blockIdx < B_F -> feature row; else center row.
// ---------------------------------------------------------------------------
__global__ void __launch_bounds__(128)
split_norm_all_k(const float* __restrict__ F, const float* __restrict__ Cn) {
    const int bx = blockIdx.x;
    const float* A;
    __nv_bfloat16 *hi, *lo;
    float* nrm;
    int row;
    if (bx < B_F) { row = bx;       A = F;  hi = g_fh; lo = g_fl; nrm = g_fn; }
    else          { row = bx - B_F; A = Cn; hi = g_ch; lo = g_cl; nrm = g_cn; }

    const int tid = threadIdx.x;
    const float4* a = (const float4*)(A + (size_t)row * D_K);
    __nv_bfloat162* H = (__nv_bfloat162*)(hi + (size_t)row * D_K);
    __nv_bfloat162* L = (__nv_bfloat162*)(lo + (size_t)row * D_K);

    float4 v[4];
#pragma unroll
    for (int j = 0; j < 4; j++) v[j] = a[tid + j * 128];   // 4 independent loads

    float s = 0.f;
#pragma unroll
    for (int j = 0; j < 4; j++) {
        const int i = tid + j * 128;
        s = fmaf(v[j].x, v[j].x, s); s = fmaf(v[j].y, v[j].y, s);
        s = fmaf(v[j].z, v[j].z, s); s = fmaf(v[j].w, v[j].w, s);
        __nv_bfloat16 h0 = __float2bfloat16(v[j].x);
        __nv_bfloat16 h1 = __float2bfloat16(v[j].y);
        __nv_bfloat16 h2 = __float2bfloat16(v[j].z);
        __nv_bfloat16 h3 = __float2bfloat16(v[j].w);
        H[i * 2 + 0] = __nv_bfloat162(h0, h1);
        H[i * 2 + 1] = __nv_bfloat162(h2, h3);
        L[i * 2 + 0] = __nv_bfloat162(__float2bfloat16(v[j].x - __bfloat162float(h0)),
                                      __float2bfloat16(v[j].y - __bfloat162float(h1)));
        L[i * 2 + 1] = __nv_bfloat162(__float2bfloat16(v[j].z - __bfloat162float(h2)),
                                      __float2bfloat16(v[j].w - __bfloat162float(h3)));
    }
#pragma unroll
    for (int off = 16; off > 0; off >>= 1)
        s += __shfl_xor_sync(0xFFFFFFFFu, s, off);
    __shared__ float wsum[4];
    if ((tid & 31) == 0) wsum[tid >> 5] = s;
    __syncthreads();
    if (tid == 0) nrm[row] = wsum[0] + wsum[1] + wsum[2] + wsum[3];
}

// ---------------------------------------------------------------------------
// Merged tensor-core distance GEMM. CTA 128x128, 4 warps of 64x64, 128 thr,
// 2-stage cp.async, 2 CTAs/SM, ONE sync per K-iter. cc upper-tri + mirror.
// ---------------------------------------------------------------------------
#define KC     32
#define NIT    (D_K / KC)            // 64
#define PADW   40
#define ROWB   (PADW * 2)            // 80 B
#define TILEB  (128 * ROWB)          // 10240 B
#define STAGEB (4 * TILEB)           // 40960 B
#define SMEMB  (2 * STAGEB)          // 81920 B -> 2 CTAs/SM
#define NCCT   136
#define NGRID  (NCCT + 512)          // 648

__global__ void __launch_bounds__(128, 2)
mma_gemm_all_k() {
    extern __shared__ char smem[];
    const uint32_t sb = smem_u32(smem);

    const int bx = blockIdx.x;
    const __nv_bfloat16 *Ah, *Al;
    const float *a2;
    float *Dout;
    int bm, bn;
    bool mirror = false;
    if (bx < NCCT) {
        int r = 0, rem = bx;
        while (rem >= 16 - r) { rem -= 16 - r; r++; }
        bm = r * 128; bn = (r + rem) * 128;
        mirror = (rem != 0);
        Ah = g_ch; Al = g_cl; a2 = g_cn; Dout = g_Dcc;
    } else {
        const int t = bx - NCCT;
        bm = (t >> 4) * 128; bn = (t & 15) * 128;
        Ah = g_fh; Al = g_fl; a2 = g_fn; Dout = g_Dfc;
    }
    const __nv_bfloat16* Bh = g_ch;
    const __nv_bfloat16* Bl = g_cl;
    const float* b2 = g_cn;

    const int tid  = threadIdx.x;
    const int lane = tid & 31;
    const int wid  = tid >> 5;
    const int wm   = wid & 1;
    const int wn   = wid >> 1;

    const __nv_bfloat16* gbase[4] = {
        Ah + (size_t)bm * D_K, Al + (size_t)bm * D_K,
        Bh + (size_t)bn * D_K, Bl + (size_t)bn * D_K };

    const int a_row = (lane & 15);
    const int a_ch  = lane >> 4;
    const uint32_t aoff = (uint32_t)((wm * 64 + a_row) * ROWB + a_ch * 16);
    const int b_row = (lane & 7) + ((lane >> 4) << 3);
    const int b_ch  = (lane >> 3) & 1;
    const uint32_t boff = (uint32_t)((wn * 64 + b_row) * ROWB + b_ch * 16);

    float acc[4][8][4];
#pragma unroll
    for (int i = 0; i < 4; i++)
#pragma unroll
        for (int j = 0; j < 8; j++)
#pragma unroll
            for (int q = 0; q < 4; q++) acc[i][j][q] = 0.f;

    auto load_stage = [&](int buf, int kc) {
        const int koff = kc * KC;
        const uint32_t sbase = sb + buf * STAGEB;
#pragma unroll
        for (int q = 0; q < 16; q++) {
            const int t   = q >> 2;
            const int rem = ((q & 3) << 7) + tid;
            const int row = rem >> 2;
            const int ch  = rem & 3;
            cp16(sbase + t * TILEB + row * ROWB + ch * 16,
                 gbase[t] + (size_t)row * D_K + koff + ch * 8);
        }
        CP_COMMIT();
    };

    load_stage(0, 0);

    for (int kc = 0; kc < NIT; kc++) {
        CP_WAIT0();          // pending group == stage kc (issued last iter)
        __syncthreads();     // data visible to all; everyone done with other buf
        if (kc + 1 < NIT) load_stage((kc + 1) & 1, kc + 1);  // safe: see sync

        const uint32_t st = sb + (kc & 1) * STAGEB;
#pragma unroll
        for (int ks = 0; ks < 2; ks++) {
            uint32_t ah[4][4], al[4][4], bh[4][4], bl[4][4];
#pragma unroll
            for (int mf = 0; mf < 4; mf++) {
                const uint32_t ao = aoff + mf * 16 * ROWB + ks * 32;
                ldsm4(ah[mf][0], ah[mf][1], ah[mf][2], ah[mf][3], st + 0 * TILEB + ao);
                ldsm4(al[mf][0], al[mf][1], al[mf][2], al[mf][3], st + 1 * TILEB + ao);
            }
#pragma unroll
            for (int nf2 = 0; nf2 < 4; nf2++) {
                const uint32_t bo = boff + nf2 * 16 * ROWB + ks * 32;
                ldsm4(bh[nf2][0], bh[nf2][1], bh[nf2][2], bh[nf2][3], st + 2 * TILEB + bo);
                ldsm4(bl[nf2][0], bl[nf2][1], bl[nf2][2], bl[nf2][3], st + 3 * TILEB + bo);
            }
#pragma unroll
            for (int mf = 0; mf < 4; mf++)
#pragma unroll
                for (int nf = 0; nf < 8; nf++) {
                    const int h = nf >> 1, o = (nf & 1) << 1;
                    mma16816(acc[mf][nf], ah[mf], bh[h][o], bh[h][o + 1]);
                }
#pragma unroll
            for (int mf = 0; mf < 4; mf++)
#pragma unroll
                for (int nf = 0; nf < 8; nf++) {
                    const int h = nf >> 1, o = (nf & 1) << 1;
                    mma16816(acc[mf][nf], ah[mf], bl[h][o], bl[h][o + 1]);
                }
#pragma unroll
            for (int mf = 0; mf < 4; mf++)
#pragma unroll
                for (int nf = 0; nf < 8; nf++) {
                    const int h = nf >> 1, o = (nf & 1) << 1;
                    mma16816(acc[mf][nf], al[mf], bh[h][o], bh[h][o + 1]);
                }
        }
    }

    // epilogue
#pragma unroll
    for (int mf = 0; mf < 4; mf++) {
        const int r0  = bm + wm * 64 + mf * 16 + (lane >> 2);
        const float am0 = a2[r0];
        const float am1 = a2[r0 + 8];
        float* out0 = Dout + (size_t)r0 * C_C;
        float* out1 = Dout + (size_t)(r0 + 8) * C_C;
#pragma unroll
        for (int nf = 0; nf < 8; nf++) {
            const int n = bn + wn * 64 + nf * 8 + ((lane & 3) << 1);
            const float b0 = b2[n], b1 = b2[n + 1];
            float2 p0, p1;
            p0.x = fmaf(-2.f, acc[mf][nf][0], am0 + b0);
            p0.y = fmaf(-2.f, acc[mf][nf][1], am0 + b1);
            p1.x = fmaf(-2.f, acc[mf][nf][2], am1 + b0);
            p1.y = fmaf(-2.f, acc[mf][nf][3], am1 + b1);
            *(float2*)(out0 + n) = p0;
            *(float2*)(out1 + n) = p1;
            if (mirror) {
                float* t0 = Dout + (size_t)n * C_C;
                float* t1 = Dout + (size_t)(n + 1) * C_C;
                t0[r0]     = p0.x;  t1[r0]     = p0.y;
                t0[r0 + 8] = p1.x;  t1[r0 + 8] = p1.y;
            }
        }
    }
}

// ---------------------------------------------------------------------------
// Per-center 3-NN: u64 lex-keys, warp butterfly merges of sorted triples.
// ---------------------------------------------------------------------------
__global__ void __launch_bounds__(256)
near3_k() {
    const int c0  = blockIdx.x;
    const int tid = threadIdx.x;
    const float* row = g_Dcc + (size_t)c0 * C_C;

    u64 t0 = KINF, t1 = KINF, t2 = KINF;
#pragma unroll
    for (int j = 0; j < C_C / 256; j++) {
        const int c = tid + j * 256;
        const u64 k = mkkey(row[c], c);
        if (k < t2) {
            t2 = k;
            if (t2 < t1) { u64 tv = t1; t1 = t2; t2 = tv;
                if (t1 < t0) { tv = t0; t0 = t1; t1 = tv; } }
        }
    }
    // warp butterfly merge
#pragma unroll
    for (int off = 16; off > 0; off >>= 1) {
        u64 b0 = __shfl_xor_sync(0xFFFFFFFFu, t0, off);
        u64 b1 = __shfl_xor_sync(0xFFFFFFFFu, t1, off);
        u64 b2 = __shfl_xor_sync(0xFFFFFFFFu, t2, off);
        merge3(t0, t1, t2, b0, b1, b2);
    }
    __shared__ u64 wtrip[8][3];
    if ((tid & 31) == 0) {
        wtrip[tid >> 5][0] = t0; wtrip[tid >> 5][1] = t1; wtrip[tid >> 5][2] = t2;
    }
    __syncthreads();
    if (tid < 32) {
        u64 a0 = KINF, a1 = KINF, a2k = KINF;
        if (tid < 8) { a0 = wtrip[tid][0]; a1 = wtrip[tid][1]; a2k = wtrip[tid][2]; }
#pragma unroll
        for (int off = 4; off > 0; off >>= 1) {
            u64 b0 = __shfl_xor_sync(0xFFFFFFFFu, a0, off);
            u64 b1 = __shfl_xor_sync(0xFFFFFFFFu, a1, off);
            u64 b2 = __shfl_xor_sync(0xFFFFFFFFu, a2k, off);
            merge3(a0, a1, a2k, b0, b1, b2);
        }
        if (tid == 0) {
            int4 p;
            p.x = (int)(uint32_t)a0; p.y = (int)(uint32_t)a1;
            p.z = (int)(uint32_t)a2k; p.w = 0;
            g_near[c0] = p;
        }
    }
}

// ---------------------------------------------------------------------------
// Per-feature-row selection: u64-key min over trusted + rank count.
// ---------------------------------------------------------------------------
__global__ void __launch_bounds__(256)
select_k() {
    const int b   = blockIdx.x;
    const int l   = b / NUMR;
    const int tid = threadIdx.x;
    const float* row = g_Dfc + (size_t)b * C_C;

    float v[C_C / 256];
    u64 best = KINF;
#pragma unroll
    for (int j = 0; j < C_C / 256; j++) {
        const int c = tid + j * 256;
        const float d = row[c];
        v[j] = d;
        const int4 nr = g_near[c];
        const bool tr = (c != l) && (nr.x != l) && (nr.y != l) && (nr.z != l);
        if (tr) best = umin64(best, mkkey(d, c));
    }
    // block min via shfl + smem
#pragma unroll
    for (int off = 16; off > 0; off >>= 1)
        best = umin64(best, __shfl_xor_sync(0xFFFFFFFFu, best, off));
    __shared__ u64 wmin[8];
    __shared__ u64 s_T;
    if ((tid & 31) == 0) wmin[tid >> 5] = best;
    __syncthreads();
    if (tid == 0) {
        u64 m = wmin[0];
#pragma unroll
        for (int w = 1; w < 8; w++) m = umin64(m, wmin[w]);
        s_T = m;
    }
    __syncthreads();
    const u64 Tkey = s_T;

    int cnt = 0;
#pragma unroll
    for (int j = 0; j < C_C / 256; j++) {
        const int c = tid + j * 256;
        if (c != l && mkkey(v[j], c) < Tkey) cnt++;
    }
#pragma unroll
    for (int off = 16; off > 0; off >>= 1)
        cnt += __shfl_xor_sync(0xFFFFFFFFu, cnt, off);
    __shared__ int wcnt[8];
    if ((tid & 31) == 0) wcnt[tid >> 5] = cnt;
    __syncthreads();

    if (tid == 0) {
        int total = 0;
#pragma unroll
        for (int w = 0; w < 8; w++) total += wcnt[w];
        const bool found = (Tkey != KINF) && (total <= MAXIT - 1);
        const float Tval = __uint_as_float((uint32_t)(Tkey >> 32));
        const float same = sqrtf(fmaxf(row[l], 0.f));
        const float md   = found ? sqrtf(fmaxf(Tval, 0.f)) : 0.f;
        g_hinge[b] = fmaxf(MARGINF + same - md, 0.f);
    }
}

// ---------------------------------------------------------------------------
__global__ void reduce_k(float* __restrict__ out) {
    const int tid = threadIdx.x;
    __shared__ float red[256];
    float s = 0.f;
    for (int i = tid; i < B_F; i += 256) s += g_hinge[i];
    red[tid] = s;
    __syncthreads();
    for (int st = 128; st > 0; st >>= 1) { if (tid < st) red[tid] += red[tid + st]; __syncthreads(); }
    if (tid == 0) out[0] = red[0] * (1.0f / (float)B_F);
}

// ---------------------------------------------------------------------------
extern "C" void kernel_launch(void* const* d_in, const int* in_sizes, int n_in,
                              void* d_out, int out_size) {
    (void)in_sizes; (void)n_in; (void)out_size;
    const float* feat = (const float*)d_in[0];
    const float* cent = (const float*)d_in[1];
    float* out = (float*)d_out;

    cudaFuncSetAttribute(mma_gemm_all_k, cudaFuncAttributeMaxDynamicSharedMemorySize, SMEMB);

    split_norm_all_k<<<B_F + C_C, 128>>>(feat, cent);
    mma_gemm_all_k<<<NGRID, 128, SMEMB>>>();
    near3_k<<<C_C, 256>>>();
    select_k<<<B_F, 256>>>();
    reduce_k<<<1, 256>>>(out);
}

// round 11
// speedup vs baseline: 1.5220x; 1.5220x over previous
#include <cuda_runtime.h>
#include <cuda_bf16.h>
#include <math.h>
#include <stdint.h>

#define D_K    2048
#define B_F    4096
#define C_C    2048
#define NUMR   2
#define NEARK  3
#define MAXIT  15
#define MARGINF 1.0f
#define IBIG   0x7FFFFFFF

typedef unsigned long long u64;
#define KINF 0xFFFFFFFFFFFFFFFFULL

// ---------------------------------------------------------------------------
// Device scratch
// ---------------------------------------------------------------------------
__device__ float g_Dfc[(size_t)B_F * C_C];   // 32 MB
__device__ float g_Dcc[(size_t)C_C * C_C];   // 16 MB
__device__ float g_fn[B_F];
__device__ float g_cn[C_C];
__device__ int4  g_near[C_C];
__device__ float g_hinge[B_F];
__device__ __nv_bfloat16 g_fh[(size_t)B_F * D_K];
__device__ __nv_bfloat16 g_fl[(size_t)B_F * D_K];
__device__ __nv_bfloat16 g_ch[(size_t)C_C * D_K];
__device__ __nv_bfloat16 g_cl[(size_t)C_C * D_K];

// ---------------------------------------------------------------------------
// Baseline-PTX helpers (sm_80+ only; plain sm_103 target has no tcgen05)
// ---------------------------------------------------------------------------
__device__ __forceinline__ uint32_t smem_u32(const void* p) {
    uint32_t a;
    asm("{ .reg .u64 t; cvta.to.shared.u64 t, %1; cvt.u32.u64 %0, t; }" : "=r"(a) : "l"(p));
    return a;
}
__device__ __forceinline__ void cp16(uint32_t s, const void* g) {
    asm volatile("cp.async.cg.shared.global [%0], [%1], 16;" :: "r"(s), "l"(g));
}
#define CP_COMMIT() asm volatile("cp.async.commit_group;" ::: "memory")
#define CP_WAIT1()  asm volatile("cp.async.wait_group 1;" ::: "memory")
#define CP_WAIT0()  asm volatile("cp.async.wait_group 0;" ::: "memory")

__device__ __forceinline__ void ldsm4(uint32_t& r0, uint32_t& r1, uint32_t& r2, uint32_t& r3,
                                      uint32_t addr) {
    asm volatile("ldmatrix.sync.aligned.m8n8.x4.shared.b16 {%0,%1,%2,%3}, [%4];"
                 : "=r"(r0), "=r"(r1), "=r"(r2), "=r"(r3) : "r"(addr));
}
__device__ __forceinline__ void mma16816(float c[4], const uint32_t a[4],
                                         uint32_t b0, uint32_t b1) {
    asm volatile("mma.sync.aligned.m16n8k16.row.col.f32.bf16.bf16.f32 "
                 "{%0,%1,%2,%3}, {%4,%5,%6,%7}, {%8,%9}, {%0,%1,%2,%3};"
                 : "+f"(c[0]), "+f"(c[1]), "+f"(c[2]), "+f"(c[3])
                 : "r"(a[0]), "r"(a[1]), "r"(a[2]), "r"(a[3]), "r"(b0), "r"(b1));
}

__device__ __forceinline__ u64 umin64(u64 a, u64 b) { return a < b ? a : b; }
__device__ __forceinline__ u64 umax64(u64 a, u64 b) { return a > b ? a : b; }
__device__ __forceinline__ u64 mkkey(float d, int idx) {
    return ((u64)__float_as_uint(d) << 32) | (uint32_t)idx;
}
// merge two sorted triples -> sorted top-3 of union (median network)
__device__ __forceinline__ void merge3(u64& a0, u64& a1, u64& a2,
                                       u64 b0, u64 b1, u64 b2) {
    u64 mx0 = umax64(a0, b0);
    u64 mn1 = umin64(a1, b1);
    u64 r0 = umin64(a0, b0);
    u64 r1 = umin64(mx0, mn1);
    u64 r2 = umin64(umax64(mx0, mn1), umin64(a2, b2));
    a0 = r0; a1 = r1; a2 = r2;
}

// ---------------------------------------------------------------------------
// Fused fp32 -> (bf16 hi, bf16 lo) split + row squared-norm (R9-proven).
// ---------------------------------------------------------------------------
__global__ void __launch_bounds__(256)
split_norm_all_k(const float* __restrict__ F, const float* __restrict__ Cn) {
    const int bx = blockIdx.x;
    const float* A;
    __nv_bfloat16 *hi, *lo;
    float* nrm;
    int row;
    if (bx < B_F) { row = bx;       A = F;  hi = g_fh; lo = g_fl; nrm = g_fn; }
    else          { row = bx - B_F; A = Cn; hi = g_ch; lo = g_cl; nrm = g_cn; }

    const int tid = threadIdx.x;
    const float4* a = (const float4*)(A + (size_t)row * D_K);
    __nv_bfloat162* H = (__nv_bfloat162*)(hi + (size_t)row * D_K);
    __nv_bfloat162* L = (__nv_bfloat162*)(lo + (size_t)row * D_K);

    float s = 0.f;
#pragma unroll
    for (int j = 0; j < 2; j++) {
        const int i = tid + j * 256;
        float4 v = a[i];
        s = fmaf(v.x, v.x, s); s = fmaf(v.y, v.y, s);
        s = fmaf(v.z, v.z, s); s = fmaf(v.w, v.w, s);
        __nv_bfloat16 h0 = __float2bfloat16(v.x);
        __nv_bfloat16 h1 = __float2bfloat16(v.y);
        __nv_bfloat16 h2 = __float2bfloat16(v.z);
        __nv_bfloat16 h3 = __float2bfloat16(v.w);
        H[i * 2 + 0] = __nv_bfloat162(h0, h1);
        H[i * 2 + 1] = __nv_bfloat162(h2, h3);
        L[i * 2 + 0] = __nv_bfloat162(__float2bfloat16(v.x - __bfloat162float(h0)),
                                      __float2bfloat16(v.y - __bfloat162float(h1)));
        L[i * 2 + 1] = __nv_bfloat162(__float2bfloat16(v.z - __bfloat162float(h2)),
                                      __float2bfloat16(v.w - __bfloat162float(h3)));
    }
    __shared__ float red[256];
    red[tid] = s; __syncthreads();
    for (int st = 128; st > 0; st >>= 1) { if (tid < st) red[tid] += red[tid + st]; __syncthreads(); }
    if (tid == 0) nrm[row] = red[0];
}

// ---------------------------------------------------------------------------
// Merged tensor-core distance GEMM (R9-proven structure). CTA 128x128,
// 4 warps of 64x64, 128 threads, 2-stage cp.async (load-before-wait, two
// syncs per iter), 2 CTAs/SM. cc upper-tri + mirror.
// ---------------------------------------------------------------------------
#define KC     32
#define NIT    (D_K / KC)            // 64
#define PADW   40
#define ROWB   (PADW * 2)            // 80 B
#define TILEB  (128 * ROWB)          // 10240 B
#define STAGEB (4 * TILEB)           // 40960 B
#define SMEMB  (2 * STAGEB)          // 81920 B -> 2 CTAs/SM
#define NCCT   136
#define NGRID  (NCCT + 512)          // 648

__global__ void __launch_bounds__(128, 2)
mma_gemm_all_k() {
    extern __shared__ char smem[];
    const uint32_t sb = smem_u32(smem);

    const int bx = blockIdx.x;
    const __nv_bfloat16 *Ah, *Al;
    const float *a2;
    float *Dout;
    int bm, bn;
    bool mirror = false;
    if (bx < NCCT) {
        int r = 0, rem = bx;
        while (rem >= 16 - r) { rem -= 16 - r; r++; }
        bm = r * 128; bn = (r + rem) * 128;
        mirror = (rem != 0);
        Ah = g_ch; Al = g_cl; a2 = g_cn; Dout = g_Dcc;
    } else {
        const int t = bx - NCCT;
        bm = (t >> 4) * 128; bn = (t & 15) * 128;
        Ah = g_fh; Al = g_fl; a2 = g_fn; Dout = g_Dfc;
    }
    const __nv_bfloat16* Bh = g_ch;
    const __nv_bfloat16* Bl = g_cl;
    const float* b2 = g_cn;

    const int tid  = threadIdx.x;
    const int lane = tid & 31;
    const int wid  = tid >> 5;
    const int wm   = wid & 1;
    const int wn   = wid >> 1;

    const __nv_bfloat16* gbase[4] = {
        Ah + (size_t)bm * D_K, Al + (size_t)bm * D_K,
        Bh + (size_t)bn * D_K, Bl + (size_t)bn * D_K };

    const int a_row = (lane & 15);
    const int a_ch  = lane >> 4;
    const uint32_t aoff = (uint32_t)((wm * 64 + a_row) * ROWB + a_ch * 16);
    const int b_row = (lane & 7) + ((lane >> 4) << 3);
    const int b_ch  = (lane >> 3) & 1;
    const uint32_t boff = (uint32_t)((wn * 64 + b_row) * ROWB + b_ch * 16);

    float acc[4][8][4];
#pragma unroll
    for (int i = 0; i < 4; i++)
#pragma unroll
        for (int j = 0; j < 8; j++)
#pragma unroll
            for (int q = 0; q < 4; q++) acc[i][j][q] = 0.f;

    auto load_stage = [&](int buf, int kc) {
        const int koff = kc * KC;
        const uint32_t sbase = sb + buf * STAGEB;
#pragma unroll
        for (int q = 0; q < 16; q++) {
            const int t   = q >> 2;
            const int rem = ((q & 3) << 7) + tid;
            const int row = rem >> 2;
            const int ch  = rem & 3;
            cp16(sbase + t * TILEB + row * ROWB + ch * 16,
                 gbase[t] + (size_t)row * D_K + koff + ch * 8);
        }
        CP_COMMIT();
    };

    load_stage(0, 0);

    for (int kc = 0; kc < NIT; kc++) {
        if (kc + 1 < NIT) load_stage((kc + 1) & 1, kc + 1);
        if (kc + 1 < NIT) CP_WAIT1(); else CP_WAIT0();
        __syncthreads();

        const uint32_t st = sb + (kc & 1) * STAGEB;
#pragma unroll
        for (int ks = 0; ks < 2; ks++) {
            uint32_t ah[4][4], al[4][4], bh[4][4], bl[4][4];
#pragma unroll
            for (int mf = 0; mf < 4; mf++) {
                const uint32_t ao = aoff + mf * 16 * ROWB + ks * 32;
                ldsm4(ah[mf][0], ah[mf][1], ah[mf][2], ah[mf][3], st + 0 * TILEB + ao);
                ldsm4(al[mf][0], al[mf][1], al[mf][2], al[mf][3], st + 1 * TILEB + ao);
            }
#pragma unroll
            for (int nf2 = 0; nf2 < 4; nf2++) {
                const uint32_t bo = boff + nf2 * 16 * ROWB + ks * 32;
                ldsm4(bh[nf2][0], bh[nf2][1], bh[nf2][2], bh[nf2][3], st + 2 * TILEB + bo);
                ldsm4(bl[nf2][0], bl[nf2][1], bl[nf2][2], bl[nf2][3], st + 3 * TILEB + bo);
            }
#pragma unroll
            for (int mf = 0; mf < 4; mf++)
#pragma unroll
                for (int nf = 0; nf < 8; nf++) {
                    const int h = nf >> 1, o = (nf & 1) << 1;
                    mma16816(acc[mf][nf], ah[mf], bh[h][o], bh[h][o + 1]);
                }
#pragma unroll
            for (int mf = 0; mf < 4; mf++)
#pragma unroll
                for (int nf = 0; nf < 8; nf++) {
                    const int h = nf >> 1, o = (nf & 1) << 1;
                    mma16816(acc[mf][nf], ah[mf], bl[h][o], bl[h][o + 1]);
                }
#pragma unroll
            for (int mf = 0; mf < 4; mf++)
#pragma unroll
                for (int nf = 0; nf < 8; nf++) {
                    const int h = nf >> 1, o = (nf & 1) << 1;
                    mma16816(acc[mf][nf], al[mf], bh[h][o], bh[h][o + 1]);
                }
        }
        __syncthreads();
    }

    // epilogue: d2 = a2[m] + b2[n] - 2*dot ; mirror for cc off-diagonal tiles
#pragma unroll
    for (int mf = 0; mf < 4; mf++) {
        const int r0  = bm + wm * 64 + mf * 16 + (lane >> 2);
        const float am0 = a2[r0];
        const float am1 = a2[r0 + 8];
        float* out0 = Dout + (size_t)r0 * C_C;
        float* out1 = Dout + (size_t)(r0 + 8) * C_C;
#pragma unroll
        for (int nf = 0; nf < 8; nf++) {
            const int n = bn + wn * 64 + nf * 8 + ((lane & 3) << 1);
            const float b0 = b2[n], b1 = b2[n + 1];
            float2 p0, p1;
            p0.x = fmaf(-2.f, acc[mf][nf][0], am0 + b0);
            p0.y = fmaf(-2.f, acc[mf][nf][1], am0 + b1);
            p1.x = fmaf(-2.f, acc[mf][nf][2], am1 + b0);
            p1.y = fmaf(-2.f, acc[mf][nf][3], am1 + b1);
            *(float2*)(out0 + n) = p0;
            *(float2*)(out1 + n) = p1;
            if (mirror) {
                float* t0 = Dout + (size_t)n * C_C;
                float* t1 = Dout + (size_t)(n + 1) * C_C;
                t0[r0]     = p0.x;  t1[r0]     = p0.y;
                t0[r0 + 8] = p1.x;  t1[r0 + 8] = p1.y;
            }
        }
    }
}

// ---------------------------------------------------------------------------
// Per-center 3-NN: u64 lex-keys + warp shfl merge3 (kept from R10; cheap).
// ---------------------------------------------------------------------------
__global__ void __launch_bounds__(256)
near3_k() {
    const int c0  = blockIdx.x;
    const int tid = threadIdx.x;
    const float* row = g_Dcc + (size_t)c0 * C_C;

    u64 t0 = KINF, t1 = KINF, t2 = KINF;
#pragma unroll
    for (int j = 0; j < C_C / 256; j++) {
        const int c = tid + j * 256;
        const u64 k = mkkey(row[c], c);
        if (k < t2) {
            t2 = k;
            if (t2 < t1) { u64 tv = t1; t1 = t2; t2 = tv;
                if (t1 < t0) { tv = t0; t0 = t1; t1 = tv; } }
        }
    }
#pragma unroll
    for (int off = 16; off > 0; off >>= 1) {
        u64 b0 = __shfl_xor_sync(0xFFFFFFFFu, t0, off);
        u64 b1 = __shfl_xor_sync(0xFFFFFFFFu, t1, off);
        u64 b2 = __shfl_xor_sync(0xFFFFFFFFu, t2, off);
        merge3(t0, t1, t2, b0, b1, b2);
    }
    __shared__ u64 wtrip[8][3];
    if ((tid & 31) == 0) {
        wtrip[tid >> 5][0] = t0; wtrip[tid >> 5][1] = t1; wtrip[tid >> 5][2] = t2;
    }
    __syncthreads();
    if (tid < 32) {
        u64 a0 = KINF, a1 = KINF, a2k = KINF;
        if (tid < 8) { a0 = wtrip[tid][0]; a1 = wtrip[tid][1]; a2k = wtrip[tid][2]; }
#pragma unroll
        for (int off = 4; off > 0; off >>= 1) {
            u64 b0 = __shfl_xor_sync(0xFFFFFFFFu, a0, off);
            u64 b1 = __shfl_xor_sync(0xFFFFFFFFu, a1, off);
            u64 b2 = __shfl_xor_sync(0xFFFFFFFFu, a2k, off);
            merge3(a0, a1, a2k, b0, b1, b2);
        }
        if (tid == 0) {
            int4 p;
            p.x = (int)(uint32_t)a0; p.y = (int)(uint32_t)a1;
            p.z = (int)(uint32_t)a2k; p.w = 0;
            g_near[c0] = p;
        }
    }
}

// ---------------------------------------------------------------------------
// Per-feature-row selection (R9-proven compound-compare form).
// ---------------------------------------------------------------------------
__global__ void __launch_bounds__(256)
select_k() {
    const int b   = blockIdx.x;
    const int l   = b / NUMR;
    const int tid = threadIdx.x;
    const float* row = g_Dfc + (size_t)b * C_C;

    float v[C_C / 256];
    float bv = INFINITY; int bi = IBIG;
#pragma unroll
    for (int j = 0; j < C_C / 256; j++) {
        const int c = tid + j * 256;
        const float d = row[c];
        v[j] = d;
        const int4 nr = g_near[c];
        const bool tr = (c != l) && (nr.x != l) && (nr.y != l) && (nr.z != l);
        if (tr && (d < bv || (d == bv && c < bi))) { bv = d; bi = c; }
    }
    __shared__ float rv[256];
    __shared__ int   ri[256];
    rv[tid] = bv; ri[tid] = bi;
    __syncthreads();
    for (int st = 128; st > 0; st >>= 1) {
        if (tid < st) {
            float v2 = rv[tid + st]; int i2 = ri[tid + st];
            if (v2 < rv[tid] || (v2 == rv[tid] && i2 < ri[tid])) { rv[tid] = v2; ri[tid] = i2; }
        }
        __syncthreads();
    }
    const float Tval = rv[0]; const int Tidx = ri[0];
    __syncthreads();

    int cnt = 0;
#pragma unroll
    for (int j = 0; j < C_C / 256; j++) {
        const int c = tid + j * 256;
        if (c != l && (v[j] < Tval || (v[j] == Tval && c < Tidx))) cnt++;
    }
    __shared__ int rc[256];
    rc[tid] = cnt;
    __syncthreads();
    for (int st = 128; st > 0; st >>= 1) { if (tid < st) rc[tid] += rc[tid + st]; __syncthreads(); }

    if (tid == 0) {
        const bool found = (Tidx < C_C) && (rc[0] <= MAXIT - 1);
        const float same = sqrtf(fmaxf(row[l], 0.f));
        const float md   = found ? sqrtf(fmaxf(Tval, 0.f)) : 0.f;
        g_hinge[b] = fmaxf(MARGINF + same - md, 0.f);
    }
}

// ---------------------------------------------------------------------------
__global__ void reduce_k(float* __restrict__ out) {
    const int tid = threadIdx.x;
    __shared__ float red[256];
    float s = 0.f;
    for (int i = tid; i < B_F; i += 256) s += g_hinge[i];
    red[tid] = s;
    __syncthreads();
    for (int st = 128; st > 0; st >>= 1) { if (tid < st) red[tid] += red[tid + st]; __syncthreads(); }
    if (tid == 0) out[0] = red[0] * (1.0f / (float)B_F);
}

// ---------------------------------------------------------------------------
extern "C" void kernel_launch(void* const* d_in, const int* in_sizes, int n_in,
                              void* d_out, int out_size) {
    (void)in_sizes; (void)n_in; (void)out_size;
    const float* feat = (const float*)d_in[0];
    const float* cent = (const float*)d_in[1];
    float* out = (float*)d_out;

    cudaFuncSetAttribute(mma_gemm_all_k, cudaFuncAttributeMaxDynamicSharedMemorySize, SMEMB);

    split_norm_all_k<<<B_F + C_C, 256>>>(feat, cent);
    mma_gemm_all_k<<<NGRID, 128, SMEMB>>>();
    near3_k<<<C_C, 256>>>();
    select_k<<<B_F, 256>>>();
    reduce_k<<<1, 256>>>(out);
}

// round 12
// speedup vs baseline: 1.5300x; 1.0053x over previous
#include <cuda_runtime.h>
#include <cuda_bf16.h>
#include <math.h>
#include <stdint.h>

#define D_K    2048
#define B_F    4096
#define C_C    2048
#define NUMR   2
#define NEARK  3
#define MAXIT  15
#define MARGINF 1.0f
#define IBIG   0x7FFFFFFF

typedef unsigned long long u64;
#define KINF 0xFFFFFFFFFFFFFFFFULL

// ---------------------------------------------------------------------------
// Device scratch
// ---------------------------------------------------------------------------
__device__ float g_Dfc[(size_t)B_F * C_C];   // 32 MB
__device__ float g_Dcc[(size_t)C_C * C_C];   // 16 MB
__device__ float g_fn[B_F];
__device__ float g_cn[C_C];
__device__ float g_hinge[B_F];
__device__ uint32_t g_untrust[C_C * (C_C / 32)];   // 512 KB bit matrix [l][c]
__device__ __nv_bfloat16 g_fh[(size_t)B_F * D_K];
__device__ __nv_bfloat16 g_fl[(size_t)B_F * D_K];
__device__ __nv_bfloat16 g_ch[(size_t)C_C * D_K];
__device__ __nv_bfloat16 g_cl[(size_t)C_C * D_K];

// ---------------------------------------------------------------------------
// Baseline-PTX helpers (sm_80+ only; plain sm_103 target has no tcgen05)
// ---------------------------------------------------------------------------
__device__ __forceinline__ uint32_t smem_u32(const void* p) {
    uint32_t a;
    asm("{ .reg .u64 t; cvta.to.shared.u64 t, %1; cvt.u32.u64 %0, t; }" : "=r"(a) : "l"(p));
    return a;
}
__device__ __forceinline__ void cp16(uint32_t s, const void* g) {
    asm volatile("cp.async.cg.shared.global [%0], [%1], 16;" :: "r"(s), "l"(g));
}
#define CP_COMMIT() asm volatile("cp.async.commit_group;" ::: "memory")
#define CP_WAIT1()  asm volatile("cp.async.wait_group 1;" ::: "memory")
#define CP_WAIT0()  asm volatile("cp.async.wait_group 0;" ::: "memory")

__device__ __forceinline__ void ldsm4(uint32_t& r0, uint32_t& r1, uint32_t& r2, uint32_t& r3,
                                      uint32_t addr) {
    asm volatile("ldmatrix.sync.aligned.m8n8.x4.shared.b16 {%0,%1,%2,%3}, [%4];"
                 : "=r"(r0), "=r"(r1), "=r"(r2), "=r"(r3) : "r"(addr));
}
__device__ __forceinline__ void mma16816(float c[4], const uint32_t a[4],
                                         uint32_t b0, uint32_t b1) {
    asm volatile("mma.sync.aligned.m16n8k16.row.col.f32.bf16.bf16.f32 "
                 "{%0,%1,%2,%3}, {%4,%5,%6,%7}, {%8,%9}, {%0,%1,%2,%3};"
                 : "+f"(c[0]), "+f"(c[1]), "+f"(c[2]), "+f"(c[3])
                 : "r"(a[0]), "r"(a[1]), "r"(a[2]), "r"(a[3]), "r"(b0), "r"(b1));
}

__device__ __forceinline__ u64 umin64(u64 a, u64 b) { return a < b ? a : b; }
__device__ __forceinline__ u64 umax64(u64 a, u64 b) { return a > b ? a : b; }
__device__ __forceinline__ u64 mkkey(float d, int idx) {
    return ((u64)__float_as_uint(d) << 32) | (uint32_t)idx;
}
// merge two sorted triples -> sorted top-3 of union (median network)
__device__ __forceinline__ void merge3(u64& a0, u64& a1, u64& a2,
                                       u64 b0, u64 b1, u64 b2) {
    u64 mx0 = umax64(a0, b0);
    u64 mn1 = umin64(a1, b1);
    u64 r0 = umin64(a0, b0);
    u64 r1 = umin64(mx0, mn1);
    u64 r2 = umin64(umax64(mx0, mn1), umin64(a2, b2));
    a0 = r0; a1 = r1; a2 = r2;
}

// ---------------------------------------------------------------------------
// Fused fp32 -> (bf16 hi,lo) split + row norm. 128 threads/row, MLP=4 loads,
// shfl reduction (2 barriers total).
// ---------------------------------------------------------------------------
__global__ void __launch_bounds__(128)
split_norm_all_k(const float* __restrict__ F, const float* __restrict__ Cn) {
    const int bx = blockIdx.x;
    const float* A;
    __nv_bfloat16 *hi, *lo;
    float* nrm;
    int row;
    if (bx < B_F) { row = bx;       A = F;  hi = g_fh; lo = g_fl; nrm = g_fn; }
    else          { row = bx - B_F; A = Cn; hi = g_ch; lo = g_cl; nrm = g_cn; }

    const int tid = threadIdx.x;
    const float4* a = (const float4*)(A + (size_t)row * D_K);
    __nv_bfloat162* H = (__nv_bfloat162*)(hi + (size_t)row * D_K);
    __nv_bfloat162* L = (__nv_bfloat162*)(lo + (size_t)row * D_K);

    float4 v[4];
#pragma unroll
    for (int j = 0; j < 4; j++) v[j] = a[tid + j * 128];   // 4 loads in flight

    float s = 0.f;
#pragma unroll
    for (int j = 0; j < 4; j++) {
        const int i = tid + j * 128;
        s = fmaf(v[j].x, v[j].x, s); s = fmaf(v[j].y, v[j].y, s);
        s = fmaf(v[j].z, v[j].z, s); s = fmaf(v[j].w, v[j].w, s);
        __nv_bfloat16 h0 = __float2bfloat16(v[j].x);
        __nv_bfloat16 h1 = __float2bfloat16(v[j].y);
        __nv_bfloat16 h2 = __float2bfloat16(v[j].z);
        __nv_bfloat16 h3 = __float2bfloat16(v[j].w);
        H[i * 2 + 0] = __nv_bfloat162(h0, h1);
        H[i * 2 + 1] = __nv_bfloat162(h2, h3);
        L[i * 2 + 0] = __nv_bfloat162(__float2bfloat16(v[j].x - __bfloat162float(h0)),
                                      __float2bfloat16(v[j].y - __bfloat162float(h1)));
        L[i * 2 + 1] = __nv_bfloat162(__float2bfloat16(v[j].z - __bfloat162float(h2)),
                                      __float2bfloat16(v[j].w - __bfloat162float(h3)));
    }
#pragma unroll
    for (int off = 16; off > 0; off >>= 1)
        s += __shfl_xor_sync(0xFFFFFFFFu, s, off);
    __shared__ float wsum[4];
    if ((tid & 31) == 0) wsum[tid >> 5] = s;
    __syncthreads();
    if (tid == 0) nrm[row] = wsum[0] + wsum[1] + wsum[2] + wsum[3];
}

// ---------------------------------------------------------------------------
// Merged tensor-core distance GEMM (frozen R9/R11 structure). CTA 128x128,
// 4 warps of 64x64, 128 threads, 2-stage cp.async, 2 CTAs/SM.
// cc upper-tri + mirror.
// ---------------------------------------------------------------------------
#define KC     32
#define NIT    (D_K / KC)            // 64
#define PADW   40
#define ROWB   (PADW * 2)            // 80 B
#define TILEB  (128 * ROWB)          // 10240 B
#define STAGEB (4 * TILEB)           // 40960 B
#define SMEMB  (2 * STAGEB)          // 81920 B -> 2 CTAs/SM
#define NCCT   136
#define NGRID  (NCCT + 512)          // 648

__global__ void __launch_bounds__(128, 2)
mma_gemm_all_k() {
    extern __shared__ char smem[];
    const uint32_t sb = smem_u32(smem);

    const int bx = blockIdx.x;
    const __nv_bfloat16 *Ah, *Al;
    const float *a2;
    float *Dout;
    int bm, bn;
    bool mirror = false;
    if (bx < NCCT) {
        int r = 0, rem = bx;
        while (rem >= 16 - r) { rem -= 16 - r; r++; }
        bm = r * 128; bn = (r + rem) * 128;
        mirror = (rem != 0);
        Ah = g_ch; Al = g_cl; a2 = g_cn; Dout = g_Dcc;
    } else {
        const int t = bx - NCCT;
        bm = (t >> 4) * 128; bn = (t & 15) * 128;
        Ah = g_fh; Al = g_fl; a2 = g_fn; Dout = g_Dfc;
    }
    const __nv_bfloat16* Bh = g_ch;
    const __nv_bfloat16* Bl = g_cl;
    const float* b2 = g_cn;

    const int tid  = threadIdx.x;
    const int lane = tid & 31;
    const int wid  = tid >> 5;
    const int wm   = wid & 1;
    const int wn   = wid >> 1;

    const __nv_bfloat16* gbase[4] = {
        Ah + (size_t)bm * D_K, Al + (size_t)bm * D_K,
        Bh + (size_t)bn * D_K, Bl + (size_t)bn * D_K };

    const int a_row = (lane & 15);
    const int a_ch  = lane >> 4;
    const uint32_t aoff = (uint32_t)((wm * 64 + a_row) * ROWB + a_ch * 16);
    const int b_row = (lane & 7) + ((lane >> 4) << 3);
    const int b_ch  = (lane >> 3) & 1;
    const uint32_t boff = (uint32_t)((wn * 64 + b_row) * ROWB + b_ch * 16);

    float acc[4][8][4];
#pragma unroll
    for (int i = 0; i < 4; i++)
#pragma unroll
        for (int j = 0; j < 8; j++)
#pragma unroll
            for (int q = 0; q < 4; q++) acc[i][j][q] = 0.f;

    auto load_stage = [&](int buf, int kc) {
        const int koff = kc * KC;
        const uint32_t sbase = sb + buf * STAGEB;
#pragma unroll
        for (int q = 0; q < 16; q++) {
            const int t   = q >> 2;
            const int rem = ((q & 3) << 7) + tid;
            const int row = rem >> 2;
            const int ch  = rem & 3;
            cp16(sbase + t * TILEB + row * ROWB + ch * 16,
                 gbase[t] + (size_t)row * D_K + koff + ch * 8);
        }
        CP_COMMIT();
    };

    load_stage(0, 0);

    for (int kc = 0; kc < NIT; kc++) {
        if (kc + 1 < NIT) load_stage((kc + 1) & 1, kc + 1);
        if (kc + 1 < NIT) CP_WAIT1(); else CP_WAIT0();
        __syncthreads();

        const uint32_t st = sb + (kc & 1) * STAGEB;
#pragma unroll
        for (int ks = 0; ks < 2; ks++) {
            uint32_t ah[4][4], al[4][4], bh[4][4], bl[4][4];
#pragma unroll
            for (int mf = 0; mf < 4; mf++) {
                const uint32_t ao = aoff + mf * 16 * ROWB + ks * 32;
                ldsm4(ah[mf][0], ah[mf][1], ah[mf][2], ah[mf][3], st + 0 * TILEB + ao);
                ldsm4(al[mf][0], al[mf][1], al[mf][2], al[mf][3], st + 1 * TILEB + ao);
            }
#pragma unroll
            for (int nf2 = 0; nf2 < 4; nf2++) {
                const uint32_t bo = boff + nf2 * 16 * ROWB + ks * 32;
                ldsm4(bh[nf2][0], bh[nf2][1], bh[nf2][2], bh[nf2][3], st + 2 * TILEB + bo);
                ldsm4(bl[nf2][0], bl[nf2][1], bl[nf2][2], bl[nf2][3], st + 3 * TILEB + bo);
            }
#pragma unroll
            for (int mf = 0; mf < 4; mf++)
#pragma unroll
                for (int nf = 0; nf < 8; nf++) {
                    const int h = nf >> 1, o = (nf & 1) << 1;
                    mma16816(acc[mf][nf], ah[mf], bh[h][o], bh[h][o + 1]);
                }
#pragma unroll
            for (int mf = 0; mf < 4; mf++)
#pragma unroll
                for (int nf = 0; nf < 8; nf++) {
                    const int h = nf >> 1, o = (nf & 1) << 1;
                    mma16816(acc[mf][nf], ah[mf], bl[h][o], bl[h][o + 1]);
                }
#pragma unroll
            for (int mf = 0; mf < 4; mf++)
#pragma unroll
                for (int nf = 0; nf < 8; nf++) {
                    const int h = nf >> 1, o = (nf & 1) << 1;
                    mma16816(acc[mf][nf], al[mf], bh[h][o], bh[h][o + 1]);
                }
        }
        __syncthreads();
    }

    // epilogue: d2 = a2[m] + b2[n] - 2*dot ; mirror for cc off-diagonal tiles
#pragma unroll
    for (int mf = 0; mf < 4; mf++) {
        const int r0  = bm + wm * 64 + mf * 16 + (lane >> 2);
        const float am0 = a2[r0];
        const float am1 = a2[r0 + 8];
        float* out0 = Dout + (size_t)r0 * C_C;
        float* out1 = Dout + (size_t)(r0 + 8) * C_C;
#pragma unroll
        for (int nf = 0; nf < 8; nf++) {
            const int n = bn + wn * 64 + nf * 8 + ((lane & 3) << 1);
            const float b0 = b2[n], b1 = b2[n + 1];
            float2 p0, p1;
            p0.x = fmaf(-2.f, acc[mf][nf][0], am0 + b0);
            p0.y = fmaf(-2.f, acc[mf][nf][1], am0 + b1);
            p1.x = fmaf(-2.f, acc[mf][nf][2], am1 + b0);
            p1.y = fmaf(-2.f, acc[mf][nf][3], am1 + b1);
            *(float2*)(out0 + n) = p0;
            *(float2*)(out1 + n) = p1;
            if (mirror) {
                float* t0 = Dout + (size_t)n * C_C;
                float* t1 = Dout + (size_t)(n + 1) * C_C;
                t0[r0]     = p0.x;  t1[r0]     = p0.y;
                t0[r0 + 8] = p1.x;  t1[r0 + 8] = p1.y;
            }
        }
    }
}

// ---------------------------------------------------------------------------
// Per-center 3-NN + scatter into untrusted bit-matrix.
// untrusted[l][c] = 1 iff l is among the 3 nearest of center c.
// ---------------------------------------------------------------------------
__global__ void __launch_bounds__(256)
near3_k() {
    const int c0  = blockIdx.x;
    const int tid = threadIdx.x;
    const float* row = g_Dcc + (size_t)c0 * C_C;

    u64 t0 = KINF, t1 = KINF, t2 = KINF;
#pragma unroll
    for (int j = 0; j < C_C / 256; j++) {
        const int c = tid + j * 256;
        const u64 k = mkkey(row[c], c);
        if (k < t2) {
            t2 = k;
            if (t2 < t1) { u64 tv = t1; t1 = t2; t2 = tv;
                if (t1 < t0) { tv = t0; t0 = t1; t1 = tv; } }
        }
    }
#pragma unroll
    for (int off = 16; off > 0; off >>= 1) {
        u64 b0 = __shfl_xor_sync(0xFFFFFFFFu, t0, off);
        u64 b1 = __shfl_xor_sync(0xFFFFFFFFu, t1, off);
        u64 b2 = __shfl_xor_sync(0xFFFFFFFFu, t2, off);
        merge3(t0, t1, t2, b0, b1, b2);
    }
    __shared__ u64 wtrip[8][3];
    if ((tid & 31) == 0) {
        wtrip[tid >> 5][0] = t0; wtrip[tid >> 5][1] = t1; wtrip[tid >> 5][2] = t2;
    }
    __syncthreads();
    if (tid < 32) {
        u64 a0 = KINF, a1 = KINF, a2k = KINF;
        if (tid < 8) { a0 = wtrip[tid][0]; a1 = wtrip[tid][1]; a2k = wtrip[tid][2]; }
#pragma unroll
        for (int off = 4; off > 0; off >>= 1) {
            u64 b0 = __shfl_xor_sync(0xFFFFFFFFu, a0, off);
            u64 b1 = __shfl_xor_sync(0xFFFFFFFFu, a1, off);
            u64 b2 = __shfl_xor_sync(0xFFFFFFFFu, a2k, off);
            merge3(a0, a1, a2k, b0, b1, b2);
        }
        // lanes 0..2 each scatter one near-index into the bit matrix
        if (tid < 3) {
            u64 key = (tid == 0) ? a0 : (tid == 1) ? a1 : a2k;
            // broadcast from lane 0's merged registers: lanes 1,2 hold their
            // own post-butterfly values which equal the global result only on
            // lane 0 -> fetch via shfl from lane 0
            u64 k0 = __shfl_sync(0x7u, a0, 0);
            u64 k1 = __shfl_sync(0x7u, a1, 0);
            u64 k2 = __shfl_sync(0x7u, a2k, 0);
            key = (tid == 0) ? k0 : (tid == 1) ? k1 : k2;
            const int ni = (int)(uint32_t)key;   // near index (the label row)
            atomicOr(&g_untrust[ni * (C_C / 32) + (c0 >> 5)], 1u << (c0 & 31));
        }
    }
}

// ---------------------------------------------------------------------------
// Per-feature-row selection: trust test = single bit probe (L1-resident row).
// ---------------------------------------------------------------------------
__global__ void __launch_bounds__(256)
select_k() {
    const int b   = blockIdx.x;
    const int l   = b / NUMR;
    const int tid = threadIdx.x;
    const float* row = g_Dfc + (size_t)b * C_C;
    const uint32_t* trow = g_untrust + l * (C_C / 32);
    const int bitpos = tid & 31;

    float v[C_C / 256];
    float bv = INFINITY; int bi = IBIG;
#pragma unroll
    for (int j = 0; j < C_C / 256; j++) {
        const int c = tid + j * 256;
        const float d = row[c];
        v[j] = d;
        const uint32_t w = trow[(tid >> 5) + j * 8];
        const bool tr = (c != l) && !((w >> bitpos) & 1u);
        if (tr && (d < bv || (d == bv && c < bi))) { bv = d; bi = c; }
    }
    __shared__ float rv[256];
    __shared__ int   ri[256];
    rv[tid] = bv; ri[tid] = bi;
    __syncthreads();
    for (int st = 128; st > 0; st >>= 1) {
        if (tid < st) {
            float v2 = rv[tid + st]; int i2 = ri[tid + st];
            if (v2 < rv[tid] || (v2 == rv[tid] && i2 < ri[tid])) { rv[tid] = v2; ri[tid] = i2; }
        }
        __syncthreads();
    }
    const float Tval = rv[0]; const int Tidx = ri[0];
    __syncthreads();

    int cnt = 0;
#pragma unroll
    for (int j = 0; j < C_C / 256; j++) {
        const int c = tid + j * 256;
        if (c != l && (v[j] < Tval || (v[j] == Tval && c < Tidx))) cnt++;
    }
    __shared__ int rc[256];
    rc[tid] = cnt;
    __syncthreads();
    for (int st = 128; st > 0; st >>= 1) { if (tid < st) rc[tid] += rc[tid + st]; __syncthreads(); }

    if (tid == 0) {
        const bool found = (Tidx < C_C) && (rc[0] <= MAXIT - 1);
        const float same = sqrtf(fmaxf(row[l], 0.f));
        const float md   = found ? sqrtf(fmaxf(Tval, 0.f)) : 0.f;
        g_hinge[b] = fmaxf(MARGINF + same - md, 0.f);
    }
}

// ---------------------------------------------------------------------------
__global__ void reduce_k(float* __restrict__ out) {
    const int tid = threadIdx.x;
    __shared__ float red[256];
    float s = 0.f;
    for (int i = tid; i < B_F; i += 256) s += g_hinge[i];
    red[tid] = s;
    __syncthreads();
    for (int st = 128; st > 0; st >>= 1) { if (tid < st) red[tid] += red[tid + st]; __syncthreads(); }
    if (tid == 0) out[0] = red[0] * (1.0f / (float)B_F);
}

// ---------------------------------------------------------------------------
extern "C" void kernel_launch(void* const* d_in, const int* in_sizes, int n_in,
                              void* d_out, int out_size) {
    (void)in_sizes; (void)n_in; (void)out_size;
    const float* feat = (const float*)d_in[0];
    const float* cent = (const float*)d_in[1];
    float* out = (float*)d_out;

    cudaFuncSetAttribute(mma_gemm_all_k, cudaFuncAttributeMaxDynamicSharedMemorySize, SMEMB);

    void* untrust_ptr = nullptr;
    cudaGetSymbolAddress(&untrust_ptr, g_untrust);
    cudaMemsetAsync(untrust_ptr, 0, sizeof(uint32_t) * C_C * (C_C / 32));

    split_norm_all_k<<<B_F + C_C, 128>>>(feat, cent);
    mma_gemm_all_k<<<NGRID, 128, SMEMB>>>();
    near3_k<<<C_C, 256>>>();
    select_k<<<B_F, 256>>>();
    reduce_k<<<1, 256>>>(out);
}

// round 13
// speedup vs baseline: 1.5896x; 1.0390x over previous
#include <cuda_runtime.h>
#include <cuda_bf16.h>
#include <math.h>
#include <stdint.h>

#define D_K    2048
#define B_F    4096
#define C_C    2048
#define NUMR   2
#define NEARK  3
#define MAXIT  15
#define MARGINF 1.0f
#define IBIG   0x7FFFFFFF

typedef unsigned long long u64;
#define KINF 0xFFFFFFFFFFFFFFFFULL

// ---------------------------------------------------------------------------
// Device scratch
// ---------------------------------------------------------------------------
__device__ float g_Dfc[(size_t)B_F * C_C];   // 32 MB
__device__ float g_Dcc[(size_t)C_C * C_C];   // 16 MB
__device__ float g_fn[B_F];
__device__ float g_cn[C_C];
__device__ float g_hinge[B_F];
__device__ uint32_t g_untrust[C_C * (C_C / 32)];   // 512 KB bit matrix [l][c]
__device__ __nv_bfloat16 g_fh[(size_t)B_F * D_K];
__device__ __nv_bfloat16 g_fl[(size_t)B_F * D_K];
__device__ __nv_bfloat16 g_ch[(size_t)C_C * D_K];
__device__ __nv_bfloat16 g_cl[(size_t)C_C * D_K];

// ---------------------------------------------------------------------------
// Baseline-PTX helpers (sm_80+ only; plain sm_103 target has no tcgen05)
// ---------------------------------------------------------------------------
__device__ __forceinline__ uint32_t smem_u32(const void* p) {
    uint32_t a;
    asm("{ .reg .u64 t; cvta.to.shared.u64 t, %1; cvt.u32.u64 %0, t; }" : "=r"(a) : "l"(p));
    return a;
}
__device__ __forceinline__ void cp16(uint32_t s, const void* g) {
    asm volatile("cp.async.cg.shared.global [%0], [%1], 16;" :: "r"(s), "l"(g));
}
#define CP_COMMIT() asm volatile("cp.async.commit_group;" ::: "memory")
#define CP_WAIT1()  asm volatile("cp.async.wait_group 1;" ::: "memory")
#define CP_WAIT0()  asm volatile("cp.async.wait_group 0;" ::: "memory")

__device__ __forceinline__ void ldsm4(uint32_t& r0, uint32_t& r1, uint32_t& r2, uint32_t& r3,
                                      uint32_t addr) {
    asm volatile("ldmatrix.sync.aligned.m8n8.x4.shared.b16 {%0,%1,%2,%3}, [%4];"
                 : "=r"(r0), "=r"(r1), "=r"(r2), "=r"(r3) : "r"(addr));
}
__device__ __forceinline__ void mma16816(float c[4], const uint32_t a[4],
                                         uint32_t b0, uint32_t b1) {
    asm volatile("mma.sync.aligned.m16n8k16.row.col.f32.bf16.bf16.f32 "
                 "{%0,%1,%2,%3}, {%4,%5,%6,%7}, {%8,%9}, {%0,%1,%2,%3};"
                 : "+f"(c[0]), "+f"(c[1]), "+f"(c[2]), "+f"(c[3])
                 : "r"(a[0]), "r"(a[1]), "r"(a[2]), "r"(a[3]), "r"(b0), "r"(b1));
}

__device__ __forceinline__ u64 umin64(u64 a, u64 b) { return a < b ? a : b; }
__device__ __forceinline__ u64 umax64(u64 a, u64 b) { return a > b ? a : b; }
__device__ __forceinline__ u64 mkkey(float d, int idx) {
    return ((u64)__float_as_uint(d) << 32) | (uint32_t)idx;
}
// merge two sorted triples -> sorted top-3 of union (median network)
__device__ __forceinline__ void merge3(u64& a0, u64& a1, u64& a2,
                                       u64 b0, u64 b1, u64 b2) {
    u64 mx0 = umax64(a0, b0);
    u64 mn1 = umin64(a1, b1);
    u64 r0 = umin64(a0, b0);
    u64 r1 = umin64(mx0, mn1);
    u64 r2 = umin64(umax64(mx0, mn1), umin64(a2, b2));
    a0 = r0; a1 = r1; a2 = r2;
}

// ---------------------------------------------------------------------------
// Fused fp32 -> (bf16 hi,lo) split + row norm (R12-proven).
// ---------------------------------------------------------------------------
__global__ void __launch_bounds__(128)
split_norm_all_k(const float* __restrict__ F, const float* __restrict__ Cn) {
    const int bx = blockIdx.x;
    const float* A;
    __nv_bfloat16 *hi, *lo;
    float* nrm;
    int row;
    if (bx < B_F) { row = bx;       A = F;  hi = g_fh; lo = g_fl; nrm = g_fn; }
    else          { row = bx - B_F; A = Cn; hi = g_ch; lo = g_cl; nrm = g_cn; }

    const int tid = threadIdx.x;
    const float4* a = (const float4*)(A + (size_t)row * D_K);
    __nv_bfloat162* H = (__nv_bfloat162*)(hi + (size_t)row * D_K);
    __nv_bfloat162* L = (__nv_bfloat162*)(lo + (size_t)row * D_K);

    float4 v[4];
#pragma unroll
    for (int j = 0; j < 4; j++) v[j] = a[tid + j * 128];

    float s = 0.f;
#pragma unroll
    for (int j = 0; j < 4; j++) {
        const int i = tid + j * 128;
        s = fmaf(v[j].x, v[j].x, s); s = fmaf(v[j].y, v[j].y, s);
        s = fmaf(v[j].z, v[j].z, s); s = fmaf(v[j].w, v[j].w, s);
        __nv_bfloat16 h0 = __float2bfloat16(v[j].x);
        __nv_bfloat16 h1 = __float2bfloat16(v[j].y);
        __nv_bfloat16 h2 = __float2bfloat16(v[j].z);
        __nv_bfloat16 h3 = __float2bfloat16(v[j].w);
        H[i * 2 + 0] = __nv_bfloat162(h0, h1);
        H[i * 2 + 1] = __nv_bfloat162(h2, h3);
        L[i * 2 + 0] = __nv_bfloat162(__float2bfloat16(v[j].x - __bfloat162float(h0)),
                                      __float2bfloat16(v[j].y - __bfloat162float(h1)));
        L[i * 2 + 1] = __nv_bfloat162(__float2bfloat16(v[j].z - __bfloat162float(h2)),
                                      __float2bfloat16(v[j].w - __bfloat162float(h3)));
    }
#pragma unroll
    for (int off = 16; off > 0; off >>= 1)
        s += __shfl_xor_sync(0xFFFFFFFFu, s, off);
    __shared__ float wsum[4];
    if ((tid & 31) == 0) wsum[tid >> 5] = s;
    __syncthreads();
    if (tid == 0) nrm[row] = wsum[0] + wsum[1] + wsum[2] + wsum[3];
}

// ---------------------------------------------------------------------------
// Merged tensor-core distance GEMM. CTA tile 128x64, 4 warps of 64x32,
// 128 threads, 2-stage cp.async (proven skeleton), 3 CTAs/SM (444 slots).
// Tiles: 272 cc upper-tri (per-element write ownership) + 1024 fc = 1296
// -> 1296/444 = 2.92 waves (near-perfect quantization).
// ---------------------------------------------------------------------------
#define KC     32
#define NIT    (D_K / KC)            // 64
#define PADW   40
#define ROWB   (PADW * 2)            // 80 B
#define ATILEB (128 * ROWB)          // 10240 B
#define BTILEB (64 * ROWB)           // 5120 B
#define OFF_AH 0
#define OFF_AL ATILEB
#define OFF_BH (2 * ATILEB)
#define OFF_BL (2 * ATILEB + BTILEB)
#define STAGEB (2 * ATILEB + 2 * BTILEB)   // 30720 B
#define SMEMB  (2 * STAGEB)                // 61440 B -> 3 CTAs/SM
#define NCCT   272                  // sum_{r=0..15} (32-2r)
#define NGRID  (NCCT + 1024)        // 1296

__global__ void __launch_bounds__(128, 3)
mma_gemm_all_k() {
    extern __shared__ char smem[];
    const uint32_t sb = smem_u32(smem);

    const int bx = blockIdx.x;
    const __nv_bfloat16 *Ah, *Al;
    const float *a2;
    float *Dout;
    int bm, bn;
    bool cc = false;
    if (bx < NCCT) {                     // cc upper triangle (64-col tiles)
        int r = 0, rem = bx;
        while (rem >= 32 - 2 * r) { rem -= 32 - 2 * r; r++; }
        bm = r * 128; bn = (2 * r + rem) * 64;
        cc = true;
        Ah = g_ch; Al = g_cl; a2 = g_cn; Dout = g_Dcc;
    } else {                             // fc: 32x32 tiles of 128x64
        const int t = bx - NCCT;
        bm = (t >> 5) * 128; bn = (t & 31) * 64;
        Ah = g_fh; Al = g_fl; a2 = g_fn; Dout = g_Dfc;
    }
    const __nv_bfloat16* Bh = g_ch;
    const __nv_bfloat16* Bl = g_cl;
    const float* b2 = g_cn;

    const int tid  = threadIdx.x;
    const int lane = tid & 31;
    const int wid  = tid >> 5;
    const int wm   = wid & 1;            // 2 m-halves of 64
    const int wn   = wid >> 1;           // 2 n-halves of 32

    const __nv_bfloat16* gA[2] = { Ah + (size_t)bm * D_K, Al + (size_t)bm * D_K };
    const __nv_bfloat16* gB[2] = { Bh + (size_t)bn * D_K, Bl + (size_t)bn * D_K };

    const int a_row = (lane & 15);
    const int a_ch  = lane >> 4;
    const uint32_t aoff = (uint32_t)((wm * 64 + a_row) * ROWB + a_ch * 16);
    const int b_row = (lane & 7) + ((lane >> 4) << 3);
    const int b_ch  = (lane >> 3) & 1;
    const uint32_t boff = (uint32_t)((wn * 32 + b_row) * ROWB + b_ch * 16);

    float acc[4][4][4];
#pragma unroll
    for (int i = 0; i < 4; i++)
#pragma unroll
        for (int j = 0; j < 4; j++)
#pragma unroll
            for (int q = 0; q < 4; q++) acc[i][j][q] = 0.f;

    auto load_stage = [&](int buf, int kc) {
        const int koff = kc * KC;
        const uint32_t sbase = sb + buf * STAGEB;
        // A tiles: 512 chunks each (q 0..3 -> Ah, 4..7 -> Al)
#pragma unroll
        for (int q = 0; q < 8; q++) {
            const int t   = q >> 2;
            const int rem = ((q & 3) << 7) + tid;
            const int row = rem >> 2;
            const int ch  = rem & 3;
            cp16(sbase + (t ? OFF_AL : OFF_AH) + row * ROWB + ch * 16,
                 gA[t] + (size_t)row * D_K + koff + ch * 8);
        }
        // B tiles: 256 chunks each (q 0..1 -> Bh, 2..3 -> Bl)
#pragma unroll
        for (int q = 0; q < 4; q++) {
            const int t   = q >> 1;
            const int rem = ((q & 1) << 7) + tid;
            const int row = rem >> 2;
            const int ch  = rem & 3;
            cp16(sbase + (t ? OFF_BL : OFF_BH) + row * ROWB + ch * 16,
                 gB[t] + (size_t)row * D_K + koff + ch * 8);
        }
        CP_COMMIT();
    };

    load_stage(0, 0);

    for (int kc = 0; kc < NIT; kc++) {
        if (kc + 1 < NIT) load_stage((kc + 1) & 1, kc + 1);
        if (kc + 1 < NIT) CP_WAIT1(); else CP_WAIT0();
        __syncthreads();

        const uint32_t st = sb + (kc & 1) * STAGEB;
#pragma unroll
        for (int ks = 0; ks < 2; ks++) {
            uint32_t ah[4][4], al[4][4], bh[2][4], bl[2][4];
#pragma unroll
            for (int mf = 0; mf < 4; mf++) {
                const uint32_t ao = aoff + mf * 16 * ROWB + ks * 32;
                ldsm4(ah[mf][0], ah[mf][1], ah[mf][2], ah[mf][3], st + OFF_AH + ao);
                ldsm4(al[mf][0], al[mf][1], al[mf][2], al[mf][3], st + OFF_AL + ao);
            }
#pragma unroll
            for (int nf2 = 0; nf2 < 2; nf2++) {
                const uint32_t bo = boff + nf2 * 16 * ROWB + ks * 32;
                ldsm4(bh[nf2][0], bh[nf2][1], bh[nf2][2], bh[nf2][3], st + OFF_BH + bo);
                ldsm4(bl[nf2][0], bl[nf2][1], bl[nf2][2], bl[nf2][3], st + OFF_BL + bo);
            }
#pragma unroll
            for (int mf = 0; mf < 4; mf++)
#pragma unroll
                for (int nf = 0; nf < 4; nf++) {
                    const int h = nf >> 1, o = (nf & 1) << 1;
                    mma16816(acc[mf][nf], ah[mf], bh[h][o], bh[h][o + 1]);
                }
#pragma unroll
            for (int mf = 0; mf < 4; mf++)
#pragma unroll
                for (int nf = 0; nf < 4; nf++) {
                    const int h = nf >> 1, o = (nf & 1) << 1;
                    mma16816(acc[mf][nf], ah[mf], bl[h][o], bl[h][o + 1]);
                }
#pragma unroll
            for (int mf = 0; mf < 4; mf++)
#pragma unroll
                for (int nf = 0; nf < 4; nf++) {
                    const int h = nf >> 1, o = (nf & 1) << 1;
                    mma16816(acc[mf][nf], al[mf], bh[h][o], bh[h][o + 1]);
                }
        }
        __syncthreads();
    }

    // epilogue: d2 = a2[m] + b2[n] - 2*dot
    // fc: plain vector stores. cc: write ownership -> direct iff n>=m,
    // mirror iff n>m (every cell written exactly once; no races).
#pragma unroll
    for (int mf = 0; mf < 4; mf++) {
        const int r0  = bm + wm * 64 + mf * 16 + (lane >> 2);
        const int r1  = r0 + 8;
        const float am0 = a2[r0];
        const float am1 = a2[r1];
        float* out0 = Dout + (size_t)r0 * C_C;
        float* out1 = Dout + (size_t)r1 * C_C;
#pragma unroll
        for (int nf = 0; nf < 4; nf++) {
            const int n = bn + wn * 32 + nf * 8 + ((lane & 3) << 1);
            const float b0 = b2[n], b1 = b2[n + 1];
            float2 p0, p1;
            p0.x = fmaf(-2.f, acc[mf][nf][0], am0 + b0);
            p0.y = fmaf(-2.f, acc[mf][nf][1], am0 + b1);
            p1.x = fmaf(-2.f, acc[mf][nf][2], am1 + b0);
            p1.y = fmaf(-2.f, acc[mf][nf][3], am1 + b1);
            if (!cc) {
                *(float2*)(out0 + n) = p0;
                *(float2*)(out1 + n) = p1;
            } else {
                // direct (n >= m)
                if (n     >= r0) out0[n]     = p0.x;
                if (n + 1 >= r0) out0[n + 1] = p0.y;
                if (n     >= r1) out1[n]     = p1.x;
                if (n + 1 >= r1) out1[n + 1] = p1.y;
                // mirror (n > m)
                if (n     > r0) Dout[(size_t)n * C_C + r0]       = p0.x;
                if (n + 1 > r0) Dout[(size_t)(n + 1) * C_C + r0] = p0.y;
                if (n     > r1) Dout[(size_t)n * C_C + r1]       = p1.x;
                if (n + 1 > r1) Dout[(size_t)(n + 1) * C_C + r1] = p1.y;
            }
        }
    }
}

// ---------------------------------------------------------------------------
// Per-center 3-NN + scatter into untrusted bit-matrix (R12-proven).
// ---------------------------------------------------------------------------
__global__ void __launch_bounds__(256)
near3_k() {
    const int c0  = blockIdx.x;
    const int tid = threadIdx.x;
    const float* row = g_Dcc + (size_t)c0 * C_C;

    u64 t0 = KINF, t1 = KINF, t2 = KINF;
#pragma unroll
    for (int j = 0; j < C_C / 256; j++) {
        const int c = tid + j * 256;
        const u64 k = mkkey(row[c], c);
        if (k < t2) {
            t2 = k;
            if (t2 < t1) { u64 tv = t1; t1 = t2; t2 = tv;
                if (t1 < t0) { tv = t0; t0 = t1; t1 = tv; } }
        }
    }
#pragma unroll
    for (int off = 16; off > 0; off >>= 1) {
        u64 b0 = __shfl_xor_sync(0xFFFFFFFFu, t0, off);
        u64 b1 = __shfl_xor_sync(0xFFFFFFFFu, t1, off);
        u64 b2 = __shfl_xor_sync(0xFFFFFFFFu, t2, off);
        merge3(t0, t1, t2, b0, b1, b2);
    }
    __shared__ u64 wtrip[8][3];
    if ((tid & 31) == 0) {
        wtrip[tid >> 5][0] = t0; wtrip[tid >> 5][1] = t1; wtrip[tid >> 5][2] = t2;
    }
    __syncthreads();
    if (tid < 32) {
        u64 a0 = KINF, a1 = KINF, a2k = KINF;
        if (tid < 8) { a0 = wtrip[tid][0]; a1 = wtrip[tid][1]; a2k = wtrip[tid][2]; }
#pragma unroll
        for (int off = 4; off > 0; off >>= 1) {
            u64 b0 = __shfl_xor_sync(0xFFFFFFFFu, a0, off);
            u64 b1 = __shfl_xor_sync(0xFFFFFFFFu, a1, off);
            u64 b2 = __shfl_xor_sync(0xFFFFFFFFu, a2k, off);
            merge3(a0, a1, a2k, b0, b1, b2);
        }
        if (tid < 3) {
            u64 k0 = __shfl_sync(0x7u, a0, 0);
            u64 k1 = __shfl_sync(0x7u, a1, 0);
            u64 k2 = __shfl_sync(0x7u, a2k, 0);
            u64 key = (tid == 0) ? k0 : (tid == 1) ? k1 : k2;
            const int ni = (int)(uint32_t)key;
            atomicOr(&g_untrust[ni * (C_C / 32) + (c0 >> 5)], 1u << (c0 & 31));
        }
    }
}

// ---------------------------------------------------------------------------
// Per-feature-row selection: bit-probe trust test (R12-proven).
// ---------------------------------------------------------------------------
__global__ void __launch_bounds__(256)
select_k() {
    const int b   = blockIdx.x;
    const int l   = b / NUMR;
    const int tid = threadIdx.x;
    const float* row = g_Dfc + (size_t)b * C_C;
    const uint32_t* trow = g_untrust + l * (C_C / 32);
    const int bitpos = tid & 31;

    float v[C_C / 256];
    float bv = INFINITY; int bi = IBIG;
#pragma unroll
    for (int j = 0; j < C_C / 256; j++) {
        const int c = tid + j * 256;
        const float d = row[c];
        v[j] = d;
        const uint32_t w = trow[(tid >> 5) + j * 8];
        const bool tr = (c != l) && !((w >> bitpos) & 1u);
        if (tr && (d < bv || (d == bv && c < bi))) { bv = d; bi = c; }
    }
    __shared__ float rv[256];
    __shared__ int   ri[256];
    rv[tid] = bv; ri[tid] = bi;
    __syncthreads();
    for (int st = 128; st > 0; st >>= 1) {
        if (tid < st) {
            float v2 = rv[tid + st]; int i2 = ri[tid + st];
            if (v2 < rv[tid] || (v2 == rv[tid] && i2 < ri[tid])) { rv[tid] = v2; ri[tid] = i2; }
        }
        __syncthreads();
    }
    const float Tval = rv[0]; const int Tidx = ri[0];
    __syncthreads();

    int cnt = 0;
#pragma unroll
    for (int j = 0; j < C_C / 256; j++) {
        const int c = tid + j * 256;
        if (c != l && (v[j] < Tval || (v[j] == Tval && c < Tidx))) cnt++;
    }
    __shared__ int rc[256];
    rc[tid] = cnt;
    __syncthreads();
    for (int st = 128; st > 0; st >>= 1) { if (tid < st) rc[tid] += rc[tid + st]; __syncthreads(); }

    if (tid == 0) {
        const bool found = (Tidx < C_C) && (rc[0] <= MAXIT - 1);
        const float same = sqrtf(fmaxf(row[l], 0.f));
        const float md   = found ? sqrtf(fmaxf(Tval, 0.f)) : 0.f;
        g_hinge[b] = fmaxf(MARGINF + same - md, 0.f);
    }
}

// ---------------------------------------------------------------------------
__global__ void reduce_k(float* __restrict__ out) {
    const int tid = threadIdx.x;
    __shared__ float red[256];
    float s = 0.f;
    for (int i = tid; i < B_F; i += 256) s += g_hinge[i];
    red[tid] = s;
    __syncthreads();
    for (int st = 128; st > 0; st >>= 1) { if (tid < st) red[tid] += red[tid + st]; __syncthreads(); }
    if (tid == 0) out[0] = red[0] * (1.0f / (float)B_F);
}

// ---------------------------------------------------------------------------
extern "C" void kernel_launch(void* const* d_in, const int* in_sizes, int n_in,
                              void* d_out, int out_size) {
    (void)in_sizes; (void)n_in; (void)out_size;
    const float* feat = (const float*)d_in[0];
    const float* cent = (const float*)d_in[1];
    float* out = (float*)d_out;

    cudaFuncSetAttribute(mma_gemm_all_k, cudaFuncAttributeMaxDynamicSharedMemorySize, SMEMB);

    void* untrust_ptr = nullptr;
    cudaGetSymbolAddress(&untrust_ptr, g_untrust);
    cudaMemsetAsync(untrust_ptr, 0, sizeof(uint32_t) * C_C * (C_C / 32));

    split_norm_all_k<<<B_F + C_C, 128>>>(feat, cent);
    mma_gemm_all_k<<<NGRID, 128, SMEMB>>>();
    near3_k<<<C_C, 256>>>();
    select_k<<<B_F, 256>>>();
    reduce_k<<<1, 256>>>(out);
}

// round 14
// speedup vs baseline: 2.0446x; 1.2862x over previous
#include <cuda_runtime.h>
#include <cuda_bf16.h>
#include <math.h>
#include <stdint.h>

#define D_K    2048
#define B_F    4096
#define C_C    2048
#define NUMR   2
#define NEARK  3
#define MAXIT  15
#define MARGINF 1.0f
#define IBIG   0x7FFFFFFF

typedef unsigned long long u64;
#define KINF 0xFFFFFFFFFFFFFFFFULL

// ---------------------------------------------------------------------------
// Device scratch
// ---------------------------------------------------------------------------
__device__ float g_Dfc[(size_t)B_F * C_C];   // 32 MB
__device__ float g_Dcc[(size_t)C_C * C_C];   // 16 MB
__device__ float g_fn[B_F];
__device__ float g_cn[C_C];
__device__ float g_hinge[B_F];
__device__ uint32_t g_untrust[C_C * (C_C / 32)];   // 512 KB bit matrix [l][c]
__device__ __nv_bfloat16 g_fh[(size_t)B_F * D_K];
__device__ __nv_bfloat16 g_fl[(size_t)B_F * D_K];
__device__ __nv_bfloat16 g_ch[(size_t)C_C * D_K];
__device__ __nv_bfloat16 g_cl[(size_t)C_C * D_K];

// ---------------------------------------------------------------------------
// Baseline-PTX helpers (sm_80+ only; plain sm_103 target has no tcgen05)
// ---------------------------------------------------------------------------
__device__ __forceinline__ uint32_t smem_u32(const void* p) {
    uint32_t a;
    asm("{ .reg .u64 t; cvta.to.shared.u64 t, %1; cvt.u32.u64 %0, t; }" : "=r"(a) : "l"(p));
    return a;
}
__device__ __forceinline__ void cp16(uint32_t s, const void* g) {
    asm volatile("cp.async.cg.shared.global [%0], [%1], 16;" :: "r"(s), "l"(g));
}
#define CP_COMMIT() asm volatile("cp.async.commit_group;" ::: "memory")
#define CP_WAIT1()  asm volatile("cp.async.wait_group 1;" ::: "memory")
#define CP_WAIT0()  asm volatile("cp.async.wait_group 0;" ::: "memory")

__device__ __forceinline__ void ldsm4(uint32_t& r0, uint32_t& r1, uint32_t& r2, uint32_t& r3,
                                      uint32_t addr) {
    asm volatile("ldmatrix.sync.aligned.m8n8.x4.shared.b16 {%0,%1,%2,%3}, [%4];"
                 : "=r"(r0), "=r"(r1), "=r"(r2), "=r"(r3) : "r"(addr));
}
__device__ __forceinline__ void mma16816(float c[4], const uint32_t a[4],
                                         uint32_t b0, uint32_t b1) {
    asm volatile("mma.sync.aligned.m16n8k16.row.col.f32.bf16.bf16.f32 "
                 "{%0,%1,%2,%3}, {%4,%5,%6,%7}, {%8,%9}, {%0,%1,%2,%3};"
                 : "+f"(c[0]), "+f"(c[1]), "+f"(c[2]), "+f"(c[3])
                 : "r"(a[0]), "r"(a[1]), "r"(a[2]), "r"(a[3]), "r"(b0), "r"(b1));
}

__device__ __forceinline__ u64 umin64(u64 a, u64 b) { return a < b ? a : b; }
__device__ __forceinline__ u64 umax64(u64 a, u64 b) { return a > b ? a : b; }
__device__ __forceinline__ u64 mkkey(float d, int idx) {
    return ((u64)__float_as_uint(d) << 32) | (uint32_t)idx;
}
// merge two sorted triples -> sorted top-3 of union (median network)
__device__ __forceinline__ void merge3(u64& a0, u64& a1, u64& a2,
                                       u64 b0, u64 b1, u64 b2) {
    u64 mx0 = umax64(a0, b0);
    u64 mn1 = umin64(a1, b1);
    u64 r0 = umin64(a0, b0);
    u64 r1 = umin64(mx0, mn1);
    u64 r2 = umin64(umax64(mx0, mn1), umin64(a2, b2));
    a0 = r0; a1 = r1; a2 = r2;
}

// ---------------------------------------------------------------------------
// Fused fp32 -> (bf16 hi,lo) split + row norm (R12-proven).
// ---------------------------------------------------------------------------
__global__ void __launch_bounds__(128)
split_norm_all_k(const float* __restrict__ F, const float* __restrict__ Cn) {
    const int bx = blockIdx.x;
    const float* A;
    __nv_bfloat16 *hi, *lo;
    float* nrm;
    int row;
    if (bx < B_F) { row = bx;       A = F;  hi = g_fh; lo = g_fl; nrm = g_fn; }
    else          { row = bx - B_F; A = Cn; hi = g_ch; lo = g_cl; nrm = g_cn; }

    const int tid = threadIdx.x;
    const float4* a = (const float4*)(A + (size_t)row * D_K);
    __nv_bfloat162* H = (__nv_bfloat162*)(hi + (size_t)row * D_K);
    __nv_bfloat162* L = (__nv_bfloat162*)(lo + (size_t)row * D_K);

    float4 v[4];
#pragma unroll
    for (int j = 0; j < 4; j++) v[j] = a[tid + j * 128];

    float s = 0.f;
#pragma unroll
    for (int j = 0; j < 4; j++) {
        const int i = tid + j * 128;
        s = fmaf(v[j].x, v[j].x, s); s = fmaf(v[j].y, v[j].y, s);
        s = fmaf(v[j].z, v[j].z, s); s = fmaf(v[j].w, v[j].w, s);
        __nv_bfloat16 h0 = __float2bfloat16(v[j].x);
        __nv_bfloat16 h1 = __float2bfloat16(v[j].y);
        __nv_bfloat16 h2 = __float2bfloat16(v[j].z);
        __nv_bfloat16 h3 = __float2bfloat16(v[j].w);
        H[i * 2 + 0] = __nv_bfloat162(h0, h1);
        H[i * 2 + 1] = __nv_bfloat162(h2, h3);
        L[i * 2 + 0] = __nv_bfloat162(__float2bfloat16(v[j].x - __bfloat162float(h0)),
                                      __float2bfloat16(v[j].y - __bfloat162float(h1)));
        L[i * 2 + 1] = __nv_bfloat162(__float2bfloat16(v[j].z - __bfloat162float(h2)),
                                      __float2bfloat16(v[j].w - __bfloat162float(h3)));
    }
#pragma unroll
    for (int off = 16; off > 0; off >>= 1)
        s += __shfl_xor_sync(0xFFFFFFFFu, s, off);
    __shared__ float wsum[4];
    if ((tid & 31) == 0) wsum[tid >> 5] = s;
    __syncthreads();
    if (tid == 0) nrm[row] = wsum[0] + wsum[1] + wsum[2] + wsum[3];
}

// ---------------------------------------------------------------------------
// Merged tensor-core distance GEMM, 2-term asymmetric bf16 split:
//   dot ~= ah.bh + al.bh   (B rounded once; a.bl dropped, err ~1e-4 rel final)
// CTA tile 128x64, 4 warps of 64x32, 128 threads, 2-stage cp.async,
// smem padded to keep the PROVEN 3 CTAs/SM schedule. cc upper-tri + mirror.
// ---------------------------------------------------------------------------
#define KC     32
#define NIT    (D_K / KC)            // 64
#define PADW   40
#define ROWB   (PADW * 2)            // 80 B
#define ATILEB (128 * ROWB)          // 10240 B
#define BTILEB (64 * ROWB)           // 5120 B
#define OFF_AH 0
#define OFF_AL ATILEB
#define OFF_BH (2 * ATILEB)
#define STAGEB (2 * ATILEB + 2 * BTILEB)   // 30720 B stride (BL slot unused pad)
#define SMEMB  (2 * STAGEB)                // 61440 B -> 3 CTAs/SM (as R13)
#define NCCT   272                  // sum_{r=0..15} (32-2r)
#define NGRID  (NCCT + 1024)        // 1296

__global__ void __launch_bounds__(128, 3)
mma_gemm_all_k() {
    extern __shared__ char smem[];
    const uint32_t sb = smem_u32(smem);

    const int bx = blockIdx.x;
    const __nv_bfloat16 *Ah, *Al;
    const float *a2;
    float *Dout;
    int bm, bn;
    bool cc = false;
    if (bx < NCCT) {                     // cc upper triangle (64-col tiles)
        int r = 0, rem = bx;
        while (rem >= 32 - 2 * r) { rem -= 32 - 2 * r; r++; }
        bm = r * 128; bn = (2 * r + rem) * 64;
        cc = true;
        Ah = g_ch; Al = g_cl; a2 = g_cn; Dout = g_Dcc;
    } else {                             // fc: 32x32 tiles of 128x64
        const int t = bx - NCCT;
        bm = (t >> 5) * 128; bn = (t & 31) * 64;
        Ah = g_fh; Al = g_fl; a2 = g_fn; Dout = g_Dfc;
    }
    const __nv_bfloat16* Bh = g_ch;
    const float* b2 = g_cn;

    const int tid  = threadIdx.x;
    const int lane = tid & 31;
    const int wid  = tid >> 5;
    const int wm   = wid & 1;            // 2 m-halves of 64
    const int wn   = wid >> 1;           // 2 n-halves of 32

    const __nv_bfloat16* gA[2] = { Ah + (size_t)bm * D_K, Al + (size_t)bm * D_K };
    const __nv_bfloat16* gBh  = Bh + (size_t)bn * D_K;

    const int a_row = (lane & 15);
    const int a_ch  = lane >> 4;
    const uint32_t aoff = (uint32_t)((wm * 64 + a_row) * ROWB + a_ch * 16);
    const int b_row = (lane & 7) + ((lane >> 4) << 3);
    const int b_ch  = (lane >> 3) & 1;
    const uint32_t boff = (uint32_t)((wn * 32 + b_row) * ROWB + b_ch * 16);

    float acc[4][4][4];
#pragma unroll
    for (int i = 0; i < 4; i++)
#pragma unroll
        for (int j = 0; j < 4; j++)
#pragma unroll
            for (int q = 0; q < 4; q++) acc[i][j][q] = 0.f;

    auto load_stage = [&](int buf, int kc) {
        const int koff = kc * KC;
        const uint32_t sbase = sb + buf * STAGEB;
        // A tiles: 512 chunks each (q 0..3 -> Ah, 4..7 -> Al)
#pragma unroll
        for (int q = 0; q < 8; q++) {
            const int t   = q >> 2;
            const int rem = ((q & 3) << 7) + tid;
            const int row = rem >> 2;
            const int ch  = rem & 3;
            cp16(sbase + (t ? OFF_AL : OFF_AH) + row * ROWB + ch * 16,
                 gA[t] + (size_t)row * D_K + koff + ch * 8);
        }
        // B hi tile: 256 chunks
#pragma unroll
        for (int q = 0; q < 2; q++) {
            const int rem = (q << 7) + tid;
            const int row = rem >> 2;
            const int ch  = rem & 3;
            cp16(sbase + OFF_BH + row * ROWB + ch * 16,
                 gBh + (size_t)row * D_K + koff + ch * 8);
        }
        CP_COMMIT();
    };

    load_stage(0, 0);

    for (int kc = 0; kc < NIT; kc++) {
        if (kc + 1 < NIT) load_stage((kc + 1) & 1, kc + 1);
        if (kc + 1 < NIT) CP_WAIT1(); else CP_WAIT0();
        __syncthreads();

        const uint32_t st = sb + (kc & 1) * STAGEB;
#pragma unroll
        for (int ks = 0; ks < 2; ks++) {
            uint32_t ah[4][4], al[4][4], bh[2][4];
#pragma unroll
            for (int mf = 0; mf < 4; mf++) {
                const uint32_t ao = aoff + mf * 16 * ROWB + ks * 32;
                ldsm4(ah[mf][0], ah[mf][1], ah[mf][2], ah[mf][3], st + OFF_AH + ao);
                ldsm4(al[mf][0], al[mf][1], al[mf][2], al[mf][3], st + OFF_AL + ao);
            }
#pragma unroll
            for (int nf2 = 0; nf2 < 2; nf2++) {
                const uint32_t bo = boff + nf2 * 16 * ROWB + ks * 32;
                ldsm4(bh[nf2][0], bh[nf2][1], bh[nf2][2], bh[nf2][3], st + OFF_BH + bo);
            }
#pragma unroll
            for (int mf = 0; mf < 4; mf++)
#pragma unroll
                for (int nf = 0; nf < 4; nf++) {
                    const int h = nf >> 1, o = (nf & 1) << 1;
                    mma16816(acc[mf][nf], ah[mf], bh[h][o], bh[h][o + 1]);
                }
#pragma unroll
            for (int mf = 0; mf < 4; mf++)
#pragma unroll
                for (int nf = 0; nf < 4; nf++) {
                    const int h = nf >> 1, o = (nf & 1) << 1;
                    mma16816(acc[mf][nf], al[mf], bh[h][o], bh[h][o + 1]);
                }
        }
        __syncthreads();
    }

    // epilogue: d2 = a2[m] + b2[n] - 2*dot
    // fc: plain vector stores. cc: ownership -> direct iff n>=m, mirror iff n>m.
#pragma unroll
    for (int mf = 0; mf < 4; mf++) {
        const int r0  = bm + wm * 64 + mf * 16 + (lane >> 2);
        const int r1  = r0 + 8;
        const float am0 = a2[r0];
        const float am1 = a2[r1];
        float* out0 = Dout + (size_t)r0 * C_C;
        float* out1 = Dout + (size_t)r1 * C_C;
#pragma unroll
        for (int nf = 0; nf < 4; nf++) {
            const int n = bn + wn * 32 + nf * 8 + ((lane & 3) << 1);
            const float b0 = b2[n], b1 = b2[n + 1];
            float2 p0, p1;
            p0.x = fmaf(-2.f, acc[mf][nf][0], am0 + b0);
            p0.y = fmaf(-2.f, acc[mf][nf][1], am0 + b1);
            p1.x = fmaf(-2.f, acc[mf][nf][2], am1 + b0);
            p1.y = fmaf(-2.f, acc[mf][nf][3], am1 + b1);
            if (!cc) {
                *(float2*)(out0 + n) = p0;
                *(float2*)(out1 + n) = p1;
            } else {
                if (n     >= r0) out0[n]     = p0.x;
                if (n + 1 >= r0) out0[n + 1] = p0.y;
                if (n     >= r1) out1[n]     = p1.x;
                if (n + 1 >= r1) out1[n + 1] = p1.y;
                if (n     > r0) Dout[(size_t)n * C_C + r0]       = p0.x;
                if (n + 1 > r0) Dout[(size_t)(n + 1) * C_C + r0] = p0.y;
                if (n     > r1) Dout[(size_t)n * C_C + r1]       = p1.x;
                if (n + 1 > r1) Dout[(size_t)(n + 1) * C_C + r1] = p1.y;
            }
        }
    }
}

// ---------------------------------------------------------------------------
// Per-center 3-NN + scatter into untrusted bit-matrix (R12-proven).
// ---------------------------------------------------------------------------
__global__ void __launch_bounds__(256)
near3_k() {
    const int c0  = blockIdx.x;
    const int tid = threadIdx.x;
    const float* row = g_Dcc + (size_t)c0 * C_C;

    u64 t0 = KINF, t1 = KINF, t2 = KINF;
#pragma unroll
    for (int j = 0; j < C_C / 256; j++) {
        const int c = tid + j * 256;
        const u64 k = mkkey(row[c], c);
        if (k < t2) {
            t2 = k;
            if (t2 < t1) { u64 tv = t1; t1 = t2; t2 = tv;
                if (t1 < t0) { tv = t0; t0 = t1; t1 = tv; } }
        }
    }
#pragma unroll
    for (int off = 16; off > 0; off >>= 1) {
        u64 b0 = __shfl_xor_sync(0xFFFFFFFFu, t0, off);
        u64 b1 = __shfl_xor_sync(0xFFFFFFFFu, t1, off);
        u64 b2 = __shfl_xor_sync(0xFFFFFFFFu, t2, off);
        merge3(t0, t1, t2, b0, b1, b2);
    }
    __shared__ u64 wtrip[8][3];
    if ((tid & 31) == 0) {
        wtrip[tid >> 5][0] = t0; wtrip[tid >> 5][1] = t1; wtrip[tid >> 5][2] = t2;
    }
    __syncthreads();
    if (tid < 32) {
        u64 a0 = KINF, a1 = KINF, a2k = KINF;
        if (tid < 8) { a0 = wtrip[tid][0]; a1 = wtrip[tid][1]; a2k = wtrip[tid][2]; }
#pragma unroll
        for (int off = 4; off > 0; off >>= 1) {
            u64 b0 = __shfl_xor_sync(0xFFFFFFFFu, a0, off);
            u64 b1 = __shfl_xor_sync(0xFFFFFFFFu, a1, off);
            u64 b2 = __shfl_xor_sync(0xFFFFFFFFu, a2k, off);
            merge3(a0, a1, a2k, b0, b1, b2);
        }
        if (tid < 3) {
            u64 k0 = __shfl_sync(0x7u, a0, 0);
            u64 k1 = __shfl_sync(0x7u, a1, 0);
            u64 k2 = __shfl_sync(0x7u, a2k, 0);
            u64 key = (tid == 0) ? k0 : (tid == 1) ? k1 : k2;
            const int ni = (int)(uint32_t)key;
            atomicOr(&g_untrust[ni * (C_C / 32) + (c0 >> 5)], 1u << (c0 & 31));
        }
    }
}

// ---------------------------------------------------------------------------
// Per-feature-row selection: bit-probe trust test (R12-proven).
// ---------------------------------------------------------------------------
__global__ void __launch_bounds__(256)
select_k() {
    const int b   = blockIdx.x;
    const int l   = b / NUMR;
    const int tid = threadIdx.x;
    const float* row = g_Dfc + (size_t)b * C_C;
    const uint32_t* trow = g_untrust + l * (C_C / 32);
    const int bitpos = tid & 31;

    float v[C_C / 256];
    float bv = INFINITY; int bi = IBIG;
#pragma unroll
    for (int j = 0; j < C_C / 256; j++) {
        const int c = tid + j * 256;
        const float d = row[c];
        v[j] = d;
        const uint32_t w = trow[(tid >> 5) + j * 8];
        const bool tr = (c != l) && !((w >> bitpos) & 1u);
        if (tr && (d < bv || (d == bv && c < bi))) { bv = d; bi = c; }
    }
    __shared__ float rv[256];
    __shared__ int   ri[256];
    rv[tid] = bv; ri[tid] = bi;
    __syncthreads();
    for (int st = 128; st > 0; st >>= 1) {
        if (tid < st) {
            float v2 = rv[tid + st]; int i2 = ri[tid + st];
            if (v2 < rv[tid] || (v2 == rv[tid] && i2 < ri[tid])) { rv[tid] = v2; ri[tid] = i2; }
        }
        __syncthreads();
    }
    const float Tval = rv[0]; const int Tidx = ri[0];
    __syncthreads();

    int cnt = 0;
#pragma unroll
    for (int j = 0; j < C_C / 256; j++) {
        const int c = tid + j * 256;
        if (c != l && (v[j] < Tval || (v[j] == Tval && c < Tidx))) cnt++;
    }
    __shared__ int rc[256];
    rc[tid] = cnt;
    __syncthreads();
    for (int st = 128; st > 0; st >>= 1) { if (tid < st) rc[tid] += rc[tid + st]; __syncthreads(); }

    if (tid == 0) {
        const bool found = (Tidx < C_C) && (rc[0] <= MAXIT - 1);
        const float same = sqrtf(fmaxf(row[l], 0.f));
        const float md   = found ? sqrtf(fmaxf(Tval, 0.f)) : 0.f;
        g_hinge[b] = fmaxf(MARGINF + same - md, 0.f);
    }
}

// ---------------------------------------------------------------------------
__global__ void reduce_k(float* __restrict__ out) {
    const int tid = threadIdx.x;
    __shared__ float red[256];
    float s = 0.f;
    for (int i = tid; i < B_F; i += 256) s += g_hinge[i];
    red[tid] = s;
    __syncthreads();
    for (int st = 128; st > 0; st >>= 1) { if (tid < st) red[tid] += red[tid + st]; __syncthreads(); }
    if (tid == 0) out[0] = red[0] * (1.0f / (float)B_F);
}

// ---------------------------------------------------------------------------
extern "C" void kernel_launch(void* const* d_in, const int* in_sizes, int n_in,
                              void* d_out, int out_size) {
    (void)in_sizes; (void)n_in; (void)out_size;
    const float* feat = (const float*)d_in[0];
    const float* cent = (const float*)d_in[1];
    float* out = (float*)d_out;

    cudaFuncSetAttribute(mma_gemm_all_k, cudaFuncAttributeMaxDynamicSharedMemorySize, SMEMB);

    void* untrust_ptr = nullptr;
    cudaGetSymbolAddress(&untrust_ptr, g_untrust);
    cudaMemsetAsync(untrust_ptr, 0, sizeof(uint32_t) * C_C * (C_C / 32));

    split_norm_all_k<<<B_F + C_C, 128>>>(feat, cent);
    mma_gemm_all_k<<<NGRID, 128, SMEMB>>>();
    near3_k<<<C_C, 256>>>();
    select_k<<<B_F, 256>>>();
    reduce_k<<<1, 256>>>(out);
}

// round 15
// speedup vs baseline: 3.2336x; 1.5815x over previous
#include <cuda_runtime.h>
#include <cuda_bf16.h>
#include <math.h>
#include <stdint.h>

#define D_K    2048
#define B_F    4096
#define C_C    2048
#define NUMR   2
#define NEARK  3
#define MAXIT  15
#define MARGINF 1.0f
#define IBIG   0x7FFFFFFF

typedef unsigned long long u64;
#define KINF 0xFFFFFFFFFFFFFFFFULL

// ---------------------------------------------------------------------------
// Device scratch
// ---------------------------------------------------------------------------
__device__ float g_Dfc[(size_t)B_F * C_C];   // 32 MB
__device__ float g_Dcc[(size_t)C_C * C_C];   // 16 MB
__device__ float g_fn[B_F];
__device__ float g_cn[C_C];
__device__ float g_hinge[B_F];
__device__ uint32_t g_untrust[C_C * (C_C / 32)];   // 512 KB bit matrix [l][c]
__device__ __nv_bfloat16 g_fh[(size_t)B_F * D_K];
__device__ __nv_bfloat16 g_ch[(size_t)C_C * D_K];

// ---------------------------------------------------------------------------
// Baseline-PTX helpers (sm_80+ only; plain sm_103 target has no tcgen05)
// ---------------------------------------------------------------------------
__device__ __forceinline__ uint32_t smem_u32(const void* p) {
    uint32_t a;
    asm("{ .reg .u64 t; cvta.to.shared.u64 t, %1; cvt.u32.u64 %0, t; }" : "=r"(a) : "l"(p));
    return a;
}
__device__ __forceinline__ void cp16(uint32_t s, const void* g) {
    asm volatile("cp.async.cg.shared.global [%0], [%1], 16;" :: "r"(s), "l"(g));
}
#define CP_COMMIT() asm volatile("cp.async.commit_group;" ::: "memory")
#define CP_WAIT1()  asm volatile("cp.async.wait_group 1;" ::: "memory")
#define CP_WAIT0()  asm volatile("cp.async.wait_group 0;" ::: "memory")

__device__ __forceinline__ void ldsm4(uint32_t& r0, uint32_t& r1, uint32_t& r2, uint32_t& r3,
                                      uint32_t addr) {
    asm volatile("ldmatrix.sync.aligned.m8n8.x4.shared.b16 {%0,%1,%2,%3}, [%4];"
                 : "=r"(r0), "=r"(r1), "=r"(r2), "=r"(r3) : "r"(addr));
}
__device__ __forceinline__ void mma16816(float c[4], const uint32_t a[4],
                                         uint32_t b0, uint32_t b1) {
    asm volatile("mma.sync.aligned.m16n8k16.row.col.f32.bf16.bf16.f32 "
                 "{%0,%1,%2,%3}, {%4,%5,%6,%7}, {%8,%9}, {%0,%1,%2,%3};"
                 : "+f"(c[0]), "+f"(c[1]), "+f"(c[2]), "+f"(c[3])
                 : "r"(a[0]), "r"(a[1]), "r"(a[2]), "r"(a[3]), "r"(b0), "r"(b1));
}

__device__ __forceinline__ u64 umin64(u64 a, u64 b) { return a < b ? a : b; }
__device__ __forceinline__ u64 umax64(u64 a, u64 b) { return a > b ? a : b; }
__device__ __forceinline__ u64 mkkey(float d, int idx) {
    return ((u64)__float_as_uint(d) << 32) | (uint32_t)idx;
}
// merge two sorted triples -> sorted top-3 of union (median network)
__device__ __forceinline__ void merge3(u64& a0, u64& a1, u64& a2,
                                       u64 b0, u64 b1, u64 b2) {
    u64 mx0 = umax64(a0, b0);
    u64 mn1 = umin64(a1, b1);
    u64 r0 = umin64(a0, b0);
    u64 r1 = umin64(mx0, mn1);
    u64 r2 = umin64(umax64(mx0, mn1), umin64(a2, b2));
    a0 = r0; a1 = r1; a2 = r2;
}

// ---------------------------------------------------------------------------
// Fused fp32 -> bf16 (hi only) + row squared-norm.
// ---------------------------------------------------------------------------
__global__ void __launch_bounds__(128)
split_norm_all_k(const float* __restrict__ F, const float* __restrict__ Cn) {
    const int bx = blockIdx.x;
    const float* A;
    __nv_bfloat16* hi;
    float* nrm;
    int row;
    if (bx < B_F) { row = bx;       A = F;  hi = g_fh; nrm = g_fn; }
    else          { row = bx - B_F; A = Cn; hi = g_ch; nrm = g_cn; }

    const int tid = threadIdx.x;
    const float4* a = (const float4*)(A + (size_t)row * D_K);
    __nv_bfloat162* H = (__nv_bfloat162*)(hi + (size_t)row * D_K);

    float4 v[4];
#pragma unroll
    for (int j = 0; j < 4; j++) v[j] = a[tid + j * 128];

    float s = 0.f;
#pragma unroll
    for (int j = 0; j < 4; j++) {
        const int i = tid + j * 128;
        s = fmaf(v[j].x, v[j].x, s); s = fmaf(v[j].y, v[j].y, s);
        s = fmaf(v[j].z, v[j].z, s); s = fmaf(v[j].w, v[j].w, s);
        H[i * 2 + 0] = __nv_bfloat162(__float2bfloat16(v[j].x), __float2bfloat16(v[j].y));
        H[i * 2 + 1] = __nv_bfloat162(__float2bfloat16(v[j].z), __float2bfloat16(v[j].w));
    }
#pragma unroll
    for (int off = 16; off > 0; off >>= 1)
        s += __shfl_xor_sync(0xFFFFFFFFu, s, off);
    __shared__ float wsum[4];
    if ((tid & 31) == 0) wsum[tid >> 5] = s;
    __syncthreads();
    if (tid == 0) nrm[row] = wsum[0] + wsum[1] + wsum[2] + wsum[3];
}

// ---------------------------------------------------------------------------
// Merged tensor-core distance GEMM, single-term bf16: dot ~= ah.bh
// (cross-term err ~1.4x the R14 2-term form; rel_err ~1e-4 final).
// CTA tile 128x64, 4 warps of 64x32, 128 threads, 2-stage cp.async,
// occupancy 4. cc upper-tri + mirror with per-element write ownership.
// ---------------------------------------------------------------------------
#define KC     32
#define NIT    (D_K / KC)            // 64
#define PADW   40
#define ROWB   (PADW * 2)            // 80 B
#define ATILEB (128 * ROWB)          // 10240 B
#define BTILEB (64 * ROWB)           // 5120 B
#define OFF_A  0
#define OFF_B  ATILEB
#define STAGEB (ATILEB + BTILEB)     // 15360 B
#define SMEMB  (2 * STAGEB)          // 30720 B -> occupancy 4 (smem allows 7)
#define NCCT   272                   // sum_{r=0..15} (32-2r)
#define NGRID  (NCCT + 1024)         // 1296

__global__ void __launch_bounds__(128, 4)
mma_gemm_all_k() {
    extern __shared__ char smem[];
    const uint32_t sb = smem_u32(smem);

    const int bx = blockIdx.x;
    const __nv_bfloat16 *Ah;
    const float *a2;
    float *Dout;
    int bm, bn;
    bool cc = false;
    if (bx < NCCT) {                     // cc upper triangle (64-col tiles)
        int r = 0, rem = bx;
        while (rem >= 32 - 2 * r) { rem -= 32 - 2 * r; r++; }
        bm = r * 128; bn = (2 * r + rem) * 64;
        cc = true;
        Ah = g_ch; a2 = g_cn; Dout = g_Dcc;
    } else {                             // fc: 32x32 tiles of 128x64
        const int t = bx - NCCT;
        bm = (t >> 5) * 128; bn = (t & 31) * 64;
        Ah = g_fh; a2 = g_fn; Dout = g_Dfc;
    }
    const __nv_bfloat16* gA  = Ah   + (size_t)bm * D_K;
    const __nv_bfloat16* gB  = g_ch + (size_t)bn * D_K;
    const float* b2 = g_cn;

    const int tid  = threadIdx.x;
    const int lane = tid & 31;
    const int wid  = tid >> 5;
    const int wm   = wid & 1;            // 2 m-halves of 64
    const int wn   = wid >> 1;           // 2 n-halves of 32

    const int a_row = (lane & 15);
    const int a_ch  = lane >> 4;
    const uint32_t aoff = (uint32_t)((wm * 64 + a_row) * ROWB + a_ch * 16);
    const int b_row = (lane & 7) + ((lane >> 4) << 3);
    const int b_ch  = (lane >> 3) & 1;
    const uint32_t boff = (uint32_t)((wn * 32 + b_row) * ROWB + b_ch * 16);

    float acc[4][4][4];
#pragma unroll
    for (int i = 0; i < 4; i++)
#pragma unroll
        for (int j = 0; j < 4; j++)
#pragma unroll
            for (int q = 0; q < 4; q++) acc[i][j][q] = 0.f;

    auto load_stage = [&](int buf, int kc) {
        const int koff = kc * KC;
        const uint32_t sbase = sb + buf * STAGEB;
        // A tile: 512 chunks (4 per thread)
#pragma unroll
        for (int q = 0; q < 4; q++) {
            const int rem = (q << 7) + tid;
            const int row = rem >> 2;
            const int ch  = rem & 3;
            cp16(sbase + OFF_A + row * ROWB + ch * 16,
                 gA + (size_t)row * D_K + koff + ch * 8);
        }
        // B tile: 256 chunks (2 per thread)
#pragma unroll
        for (int q = 0; q < 2; q++) {
            const int rem = (q << 7) + tid;
            const int row = rem >> 2;
            const int ch  = rem & 3;
            cp16(sbase + OFF_B + row * ROWB + ch * 16,
                 gB + (size_t)row * D_K + koff + ch * 8);
        }
        CP_COMMIT();
    };

    load_stage(0, 0);

    for (int kc = 0; kc < NIT; kc++) {
        if (kc + 1 < NIT) load_stage((kc + 1) & 1, kc + 1);
        if (kc + 1 < NIT) CP_WAIT1(); else CP_WAIT0();
        __syncthreads();

        const uint32_t st = sb + (kc & 1) * STAGEB;
#pragma unroll
        for (int ks = 0; ks < 2; ks++) {
            uint32_t ah[4][4], bh[2][4];
#pragma unroll
            for (int mf = 0; mf < 4; mf++) {
                const uint32_t ao = aoff + mf * 16 * ROWB + ks * 32;
                ldsm4(ah[mf][0], ah[mf][1], ah[mf][2], ah[mf][3], st + OFF_A + ao);
            }
#pragma unroll
            for (int nf2 = 0; nf2 < 2; nf2++) {
                const uint32_t bo = boff + nf2 * 16 * ROWB + ks * 32;
                ldsm4(bh[nf2][0], bh[nf2][1], bh[nf2][2], bh[nf2][3], st + OFF_B + bo);
            }
#pragma unroll
            for (int mf = 0; mf < 4; mf++)
#pragma unroll
                for (int nf = 0; nf < 4; nf++) {
                    const int h = nf >> 1, o = (nf & 1) << 1;
                    mma16816(acc[mf][nf], ah[mf], bh[h][o], bh[h][o + 1]);
                }
        }
        __syncthreads();
    }

    // epilogue: d2 = a2[m] + b2[n] - 2*dot
    // fc: plain vector stores. cc: ownership -> direct iff n>=m, mirror iff n>m.
#pragma unroll
    for (int mf = 0; mf < 4; mf++) {
        const int r0  = bm + wm * 64 + mf * 16 + (lane >> 2);
        const int r1  = r0 + 8;
        const float am0 = a2[r0];
        const float am1 = a2[r1];
        float* out0 = Dout + (size_t)r0 * C_C;
        float* out1 = Dout + (size_t)r1 * C_C;
#pragma unroll
        for (int nf = 0; nf < 4; nf++) {
            const int n = bn + wn * 32 + nf * 8 + ((lane & 3) << 1);
            const float b0 = b2[n], b1 = b2[n + 1];
            float2 p0, p1;
            p0.x = fmaf(-2.f, acc[mf][nf][0], am0 + b0);
            p0.y = fmaf(-2.f, acc[mf][nf][1], am0 + b1);
            p1.x = fmaf(-2.f, acc[mf][nf][2], am1 + b0);
            p1.y = fmaf(-2.f, acc[mf][nf][3], am1 + b1);
            if (!cc) {
                *(float2*)(out0 + n) = p0;
                *(float2*)(out1 + n) = p1;
            } else {
                if (n     >= r0) out0[n]     = p0.x;
                if (n + 1 >= r0) out0[n + 1] = p0.y;
                if (n     >= r1) out1[n]     = p1.x;
                if (n + 1 >= r1) out1[n + 1] = p1.y;
                if (n     > r0) Dout[(size_t)n * C_C + r0]       = p0.x;
                if (n + 1 > r0) Dout[(size_t)(n + 1) * C_C + r0] = p0.y;
                if (n     > r1) Dout[(size_t)n * C_C + r1]       = p1.x;
                if (n + 1 > r1) Dout[(size_t)(n + 1) * C_C + r1] = p1.y;
            }
        }
    }
}

// ---------------------------------------------------------------------------
// Per-center 3-NN + scatter into untrusted bit-matrix (R12-proven).
// ---------------------------------------------------------------------------
__global__ void __launch_bounds__(256)
near3_k() {
    const int c0  = blockIdx.x;
    const int tid = threadIdx.x;
    const float* row = g_Dcc + (size_t)c0 * C_C;

    u64 t0 = KINF, t1 = KINF, t2 = KINF;
#pragma unroll
    for (int j = 0; j < C_C / 256; j++) {
        const int c = tid + j * 256;
        const u64 k = mkkey(row[c], c);
        if (k < t2) {
            t2 = k;
            if (t2 < t1) { u64 tv = t1; t1 = t2; t2 = tv;
                if (t1 < t0) { tv = t0; t0 = t1; t1 = tv; } }
        }
    }
#pragma unroll
    for (int off = 16; off > 0; off >>= 1) {
        u64 b0 = __shfl_xor_sync(0xFFFFFFFFu, t0, off);
        u64 b1 = __shfl_xor_sync(0xFFFFFFFFu, t1, off);
        u64 b2 = __shfl_xor_sync(0xFFFFFFFFu, t2, off);
        merge3(t0, t1, t2, b0, b1, b2);
    }
    __shared__ u64 wtrip[8][3];
    if ((tid & 31) == 0) {
        wtrip[tid >> 5][0] = t0; wtrip[tid >> 5][1] = t1; wtrip[tid >> 5][2] = t2;
    }
    __syncthreads();
    if (tid < 32) {
        u64 a0 = KINF, a1 = KINF, a2k = KINF;
        if (tid < 8) { a0 = wtrip[tid][0]; a1 = wtrip[tid][1]; a2k = wtrip[tid][2]; }
#pragma unroll
        for (int off = 4; off > 0; off >>= 1) {
            u64 b0 = __shfl_xor_sync(0xFFFFFFFFu, a0, off);
            u64 b1 = __shfl_xor_sync(0xFFFFFFFFu, a1, off);
            u64 b2 = __shfl_xor_sync(0xFFFFFFFFu, a2k, off);
            merge3(a0, a1, a2k, b0, b1, b2);
        }
        if (tid < 3) {
            u64 k0 = __shfl_sync(0x7u, a0, 0);
            u64 k1 = __shfl_sync(0x7u, a1, 0);
            u64 k2 = __shfl_sync(0x7u, a2k, 0);
            u64 key = (tid == 0) ? k0 : (tid == 1) ? k1 : k2;
            const int ni = (int)(uint32_t)key;
            atomicOr(&g_untrust[ni * (C_C / 32) + (c0 >> 5)], 1u << (c0 & 31));
        }
    }
}

// ---------------------------------------------------------------------------
// Per-feature-row selection: bit-probe trust test (R12-proven).
// ---------------------------------------------------------------------------
__global__ void __launch_bounds__(256)
select_k() {
    const int b   = blockIdx.x;
    const int l   = b / NUMR;
    const int tid = threadIdx.x;
    const float* row = g_Dfc + (size_t)b * C_C;
    const uint32_t* trow = g_untrust + l * (C_C / 32);
    const int bitpos = tid & 31;

    float v[C_C / 256];
    float bv = INFINITY; int bi = IBIG;
#pragma unroll
    for (int j = 0; j < C_C / 256; j++) {
        const int c = tid + j * 256;
        const float d = row[c];
        v[j] = d;
        const uint32_t w = trow[(tid >> 5) + j * 8];
        const bool tr = (c != l) && !((w >> bitpos) & 1u);
        if (tr && (d < bv || (d == bv && c < bi))) { bv = d; bi = c; }
    }
    __shared__ float rv[256];
    __shared__ int   ri[256];
    rv[tid] = bv; ri[tid] = bi;
    __syncthreads();
    for (int st = 128; st > 0; st >>= 1) {
        if (tid < st) {
            float v2 = rv[tid + st]; int i2 = ri[tid + st];
            if (v2 < rv[tid] || (v2 == rv[tid] && i2 < ri[tid])) { rv[tid] = v2; ri[tid] = i2; }
        }
        __syncthreads();
    }
    const float Tval = rv[0]; const int Tidx = ri[0];
    __syncthreads();

    int cnt = 0;
#pragma unroll
    for (int j = 0; j < C_C / 256; j++) {
        const int c = tid + j * 256;
        if (c != l && (v[j] < Tval || (v[j] == Tval && c < Tidx))) cnt++;
    }
    __shared__ int rc[256];
    rc[tid] = cnt;
    __syncthreads();
    for (int st = 128; st > 0; st >>= 1) { if (tid < st) rc[tid] += rc[tid + st]; __syncthreads(); }

    if (tid == 0) {
        const bool found = (Tidx < C_C) && (rc[0] <= MAXIT - 1);
        const float same = sqrtf(fmaxf(row[l], 0.f));
        const float md   = found ? sqrtf(fmaxf(Tval, 0.f)) : 0.f;
        g_hinge[b] = fmaxf(MARGINF + same - md, 0.f);
    }
}

// ---------------------------------------------------------------------------
__global__ void reduce_k(float* __restrict__ out) {
    const int tid = threadIdx.x;
    __shared__ float red[256];
    float s = 0.f;
    for (int i = tid; i < B_F; i += 256) s += g_hinge[i];
    red[tid] = s;
    __syncthreads();
    for (int st = 128; st > 0; st >>= 1) { if (tid < st) red[tid] += red[tid + st]; __syncthreads(); }
    if (tid == 0) out[0] = red[0] * (1.0f / (float)B_F);
}

// ---------------------------------------------------------------------------
extern "C" void kernel_launch(void* const* d_in, const int* in_sizes, int n_in,
                              void* d_out, int out_size) {
    (void)in_sizes; (void)n_in; (void)out_size;
    const float* feat = (const float*)d_in[0];
    const float* cent = (const float*)d_in[1];
    float* out = (float*)d_out;

    cudaFuncSetAttribute(mma_gemm_all_k, cudaFuncAttributeMaxDynamicSharedMemorySize, SMEMB);

    void* untrust_ptr = nullptr;
    cudaGetSymbolAddress(&untrust_ptr, g_untrust);
    cudaMemsetAsync(untrust_ptr, 0, sizeof(uint32_t) * C_C * (C_C / 32));

    split_norm_all_k<<<B_F + C_C, 128>>>(feat, cent);
    mma_gemm_all_k<<<NGRID, 128, SMEMB>>>();
    near3_k<<<C_C, 256>>>();
    select_k<<<B_F, 256>>>();
    reduce_k<<<1, 256>>>(out);
}